// round 1
// baseline (speedup 1.0000x reference)
#include <cuda_runtime.h>
#include <cstdint>

// ---------------------------------------------------------------------------
// PNN_43095701848191
//   train_data  f32 [8192, 1024]   (d_in[0])
//   train_label i32 [8192]         (d_in[1])  (jax canonicalizes int64->int32)
//   test_data   f32 [4096, 1024]   (d_in[2])
// Pipeline: row L2 norms -> fused NT-GEMM (dot of normalized rows) with
// epilogue  d2 = 2-2*dot, D = sqrt(d2), g = exp(-2 D), per-class column sums
// -> finalize (prob normalize + argmax).
// GEMM uses packed fma.rn.f32x2 (2 FMA lanes / issue slot on sm_10x; plain
// 3-reg FFMA is half-rate). A operand stored duplicated in SMEM so the packed
// pairs need no per-step register shuffling.
// ---------------------------------------------------------------------------

#define TRAIN_N 8192
#define TEST_P  4096
#define KDIM    1024

#define BM 128   // test rows per CTA tile
#define BN 128   // train rows per CTA tile
#define BK 8

__device__ float g_invtr[TRAIN_N];
__device__ float g_invte[TEST_P];
__device__ float g_tot[TEST_P];
__device__ float g_s1[TEST_P];

// ---------------------------------------------------------------------------
// Kernel 1: per-row inverse L2 norms; also zero the class accumulators.
// ---------------------------------------------------------------------------
__global__ void norm_kernel(const float* __restrict__ train,
                            const float* __restrict__ test) {
    int b = blockIdx.x;
    const float* row = (b < TRAIN_N) ? (train + (size_t)b * KDIM)
                                     : (test + (size_t)(b - TRAIN_N) * KDIM);
    int t = threadIdx.x;                       // 256 threads, 1024 floats/row
    float4 v = ((const float4*)row)[t];
    float s = v.x * v.x + v.y * v.y + v.z * v.z + v.w * v.w;
    #pragma unroll
    for (int o = 16; o; o >>= 1) s += __shfl_xor_sync(0xffffffffu, s, o);
    __shared__ float ws[8];
    if ((t & 31) == 0) ws[t >> 5] = s;
    __syncthreads();
    if (t < 8) {
        float x = ws[t];
        #pragma unroll
        for (int o = 4; o; o >>= 1) x += __shfl_xor_sync(0xffu, x, o);
        if (t == 0) {
            float inv = rsqrtf(x);
            if (b < TRAIN_N) g_invtr[b] = inv;
            else             g_invte[b - TRAIN_N] = inv;
        }
    }
    if (t == 0 && b < TEST_P) { g_tot[b] = 0.0f; g_s1[b] = 0.0f; }
}

// packed f32x2 fused multiply-add (PTX-only on Blackwell)
#define FMA2(d, a, b) \
    asm("fma.rn.f32x2 %0, %1, %2, %0;" : "+l"(d) : "l"(a), "l"(b))

// ---------------------------------------------------------------------------
// Kernel 2: fused GEMM + PNN epilogue.
//   A = test [4096,1024], B = train [8192,1024], both K-contiguous (NT GEMM).
//   blockIdx.y -> test tile (32), blockIdx.x -> train tile (64).
//   256 threads = 16x16; each thread: 8 rows x 8 cols (rows as dup'd scalars,
//   cols as packed pairs) -> 32 fma.rn.f32x2 per k-step.
// ---------------------------------------------------------------------------
__global__ __launch_bounds__(256, 2)
void pnn_gemm(const float* __restrict__ A, const float* __restrict__ B,
              const int* __restrict__ label) {
    __shared__ __align__(16) float AsD[2][BK][2 * BM];  // duplicated test rows
    __shared__ __align__(16) float Bs[2][BK][BN];
    __shared__ float s_ivte[BM];
    __shared__ float s_ivtr[BN];
    __shared__ float s_lab[BN];

    const int tid = threadIdx.x;
    const int tx  = tid & 15;         // col group
    const int ty  = tid >> 4;         // row group
    const int rowBase = blockIdx.y * BM;   // test rows
    const int colBase = blockIdx.x * BN;   // train rows

    if (tid < BM) {
        s_ivte[tid] = g_invte[rowBase + tid];
    } else {
        int c = tid - BM;
        s_ivtr[c] = g_invtr[colBase + c];
        s_lab[c]  = (float)label[colBase + c];
    }

    // global load mapping: thread -> (row = tid>>1, 4 consecutive k at (tid&1)*4)
    const int lrow = tid >> 1;
    const int lk4  = (tid & 1);       // which float4 within the 8-wide k chunk
    const float4* A4 = (const float4*)(A + (size_t)(rowBase + lrow) * KDIM) + lk4;
    const float4* B4 = (const float4*)(B + (size_t)(colBase + lrow) * KDIM) + lk4;

    // preload chunk 0
    float4 va = A4[0];
    float4 vb = B4[0];
    {
        const int k0 = lk4 * 4;
        float2* ad = (float2*)&AsD[0][k0][2 * lrow];
        ad[0]          = make_float2(va.x, va.x);
        *(float2*)&AsD[0][k0 + 1][2 * lrow] = make_float2(va.y, va.y);
        *(float2*)&AsD[0][k0 + 2][2 * lrow] = make_float2(va.z, va.z);
        *(float2*)&AsD[0][k0 + 3][2 * lrow] = make_float2(va.w, va.w);
        Bs[0][k0][lrow]     = vb.x;
        Bs[0][k0 + 1][lrow] = vb.y;
        Bs[0][k0 + 2][lrow] = vb.z;
        Bs[0][k0 + 3][lrow] = vb.w;
    }
    __syncthreads();

    unsigned long long acc[8][4];
    #pragma unroll
    for (int r = 0; r < 8; ++r)
        #pragma unroll
        for (int p = 0; p < 4; ++p) acc[r][p] = 0ULL;

    const int NCHUNK = KDIM / BK;     // 128
    int buf = 0;
    for (int t = 0; t < NCHUNK; ++t) {
        float4 na, nb;
        if (t + 1 < NCHUNK) {         // prefetch next chunk (L2-resident)
            na = A4[(t + 1) * 2];
            nb = B4[(t + 1) * 2];
        }
        #pragma unroll
        for (int k = 0; k < BK; ++k) {
            const ulonglong2* ap = (const ulonglong2*)&AsD[buf][k][16 * ty];
            ulonglong2 a0 = ap[0], a1 = ap[1], a2 = ap[2], a3 = ap[3];
            const ulonglong2* bp = (const ulonglong2*)&Bs[buf][k][8 * tx];
            ulonglong2 b0 = bp[0], b1 = bp[1];
            FMA2(acc[0][0], a0.x, b0.x); FMA2(acc[0][1], a0.x, b0.y);
            FMA2(acc[0][2], a0.x, b1.x); FMA2(acc[0][3], a0.x, b1.y);
            FMA2(acc[1][0], a0.y, b0.x); FMA2(acc[1][1], a0.y, b0.y);
            FMA2(acc[1][2], a0.y, b1.x); FMA2(acc[1][3], a0.y, b1.y);
            FMA2(acc[2][0], a1.x, b0.x); FMA2(acc[2][1], a1.x, b0.y);
            FMA2(acc[2][2], a1.x, b1.x); FMA2(acc[2][3], a1.x, b1.y);
            FMA2(acc[3][0], a1.y, b0.x); FMA2(acc[3][1], a1.y, b0.y);
            FMA2(acc[3][2], a1.y, b1.x); FMA2(acc[3][3], a1.y, b1.y);
            FMA2(acc[4][0], a2.x, b0.x); FMA2(acc[4][1], a2.x, b0.y);
            FMA2(acc[4][2], a2.x, b1.x); FMA2(acc[4][3], a2.x, b1.y);
            FMA2(acc[5][0], a2.y, b0.x); FMA2(acc[5][1], a2.y, b0.y);
            FMA2(acc[5][2], a2.y, b1.x); FMA2(acc[5][3], a2.y, b1.y);
            FMA2(acc[6][0], a3.x, b0.x); FMA2(acc[6][1], a3.x, b0.y);
            FMA2(acc[6][2], a3.x, b1.x); FMA2(acc[6][3], a3.x, b1.y);
            FMA2(acc[7][0], a3.y, b0.x); FMA2(acc[7][1], a3.y, b0.y);
            FMA2(acc[7][2], a3.y, b1.x); FMA2(acc[7][3], a3.y, b1.y);
        }
        if (t + 1 < NCHUNK) {
            const int nbuf = buf ^ 1;
            const int k0 = lk4 * 4;
            *(float2*)&AsD[nbuf][k0][2 * lrow]     = make_float2(na.x, na.x);
            *(float2*)&AsD[nbuf][k0 + 1][2 * lrow] = make_float2(na.y, na.y);
            *(float2*)&AsD[nbuf][k0 + 2][2 * lrow] = make_float2(na.z, na.z);
            *(float2*)&AsD[nbuf][k0 + 3][2 * lrow] = make_float2(na.w, na.w);
            Bs[nbuf][k0][lrow]     = nb.x;
            Bs[nbuf][k0 + 1][lrow] = nb.y;
            Bs[nbuf][k0 + 2][lrow] = nb.z;
            Bs[nbuf][k0 + 3][lrow] = nb.w;
            __syncthreads();
            buf = nbuf;
        }
    }

    // ---- epilogue: dot -> distance -> Gauss -> class sums ----
    #pragma unroll
    for (int r = 0; r < 8; ++r) {
        const int grow = ty * 8 + r;          // row within tile
        const float ivte = s_ivte[grow];
        float tot = 0.0f, s1 = 0.0f;
        #pragma unroll
        for (int p = 0; p < 4; ++p) {
            float c0, c1;
            asm("mov.b64 {%0, %1}, %2;" : "=f"(c0), "=f"(c1) : "l"(acc[r][p]));
            const int j0 = tx * 8 + 2 * p;
            {
                float dot = c0 * ivte * s_ivtr[j0];
                float d2  = fmaxf(2.0f - 2.0f * dot, 0.0f);
                float g   = __expf(-2.0f * __fsqrt_rn(d2));
                tot += g;  s1 += g * s_lab[j0];
            }
            {
                float dot = c1 * ivte * s_ivtr[j0 + 1];
                float d2  = fmaxf(2.0f - 2.0f * dot, 0.0f);
                float g   = __expf(-2.0f * __fsqrt_rn(d2));
                tot += g;  s1 += g * s_lab[j0 + 1];
            }
        }
        // reduce across the 16 tx-threads (lanes [0..15] / [16..31] of warp)
        #pragma unroll
        for (int o = 1; o < 16; o <<= 1) {
            tot += __shfl_xor_sync(0xffffffffu, tot, o);
            s1  += __shfl_xor_sync(0xffffffffu, s1, o);
        }
        if (tx == 0) {
            atomicAdd(&g_tot[rowBase + grow], tot);
            atomicAdd(&g_s1[rowBase + grow], s1);
        }
    }
}

// ---------------------------------------------------------------------------
// Kernel 3: normalize probabilities, argmax, write output.
// Output layout adapts to out_size:
//   12288: [results(4096) | prob(4096x2)]   (tuple concat, most likely)
//    8192: prob only
//    4096: results only
// ---------------------------------------------------------------------------
__global__ void finalize_kernel(float* __restrict__ out, int out_size) {
    int i = blockIdx.x * blockDim.x + threadIdx.x;
    if (i >= TEST_P) return;
    float tot = g_tot[i];
    float s1  = g_s1[i];
    float s0  = tot - s1;
    float p0  = s0 / tot;
    float p1  = s1 / tot;
    float res = (p1 > p0) ? 1.0f : 0.0f;   // jnp.argmax: first max wins on tie
    if (out_size >= TEST_P * 3) {
        out[i] = res;
        out[TEST_P + 2 * i]     = p0;
        out[TEST_P + 2 * i + 1] = p1;
    } else if (out_size == TEST_P * 2) {
        out[2 * i]     = p0;
        out[2 * i + 1] = p1;
    } else {
        out[i] = res;
    }
}

extern "C" void kernel_launch(void* const* d_in, const int* in_sizes, int n_in,
                              void* d_out, int out_size) {
    const float* train = (const float*)d_in[0];
    const int*   label = (const int*)d_in[1];
    const float* test  = (const float*)d_in[2];

    norm_kernel<<<TRAIN_N + TEST_P, 256>>>(train, test);

    dim3 grid(TRAIN_N / BN, TEST_P / BM);   // (64, 32)
    pnn_gemm<<<grid, 256>>>(test, train, label);

    finalize_kernel<<<(TEST_P + 255) / 256, 256>>>((float*)d_out, out_size);
}

// round 4
// speedup vs baseline: 3.1881x; 3.1881x over previous
#include <cuda_runtime.h>
#include <cuda_bf16.h>
#include <cstdint>

// ---------------------------------------------------------------------------
// PNN_43095701848191 — mma.sync (HMMA) bf16x3-split implementation.
// tcgen05 is unavailable: the harness's ptxas target is plain sm_100 (no 'a'),
// which rejects all tcgen05/.cta_group features. mma.sync.m16n8k16.bf16 is
// sm_80+ and runs on the Blackwell tensor pipe.
//
//   train_data  f32 [8192, 1024]
//   train_label i32 [8192]
//   test_data   f32 [4096, 1024]
//
// prep:   normalize rows, split x = hi + lo (bf16), K-concat:
//           A' = [hi, hi, lo]  (test,  4096 x 3072)
//           B' = [hi, lo, hi]  (train, 8192 x 3072)
//         dot(A'_i, B'_j) = hi.hi + hi.lo + lo.hi  ~ fp32-accurate dot.
// gemm:   CTA tile 128x256 (8 warps x 64x64 warp tiles), K-chunks of 64
//         (128 B per row, SW128 swizzle), 4-stage cp.async pipeline,
//         ldmatrix.x4 fragments + mma.sync.m16n8k16. Epilogue computes
//         g = exp(-2*sqrt(max(2-2*dot,0))) and per-class row sums (atomics).
// final:  prob normalize + argmax.
// ---------------------------------------------------------------------------

#define TRAIN_N 8192
#define TEST_P  4096
#define KDIM    1024
#define KSPLIT  3072
#define KPITCH  (KSPLIT * 2)      // bytes per row

#define MT 128
#define NT 256
#define KC 64                     // k elems per chunk (128 B per row)
#define NCHUNK (KSPLIT / KC)      // 48
#define STAGES 4

__device__ __align__(16) __nv_bfloat16 g_A[TEST_P * KSPLIT];
__device__ __align__(16) __nv_bfloat16 g_B[TRAIN_N * KSPLIT];
__device__ float g_tot[TEST_P];
__device__ float g_s1[TEST_P];

__device__ __forceinline__ uint32_t smem_u32(const void* p) {
    uint32_t a;
    asm("{ .reg .u64 t; cvta.to.shared.u64 t, %1; cvt.u32.u64 %0, t; }"
        : "=r"(a) : "l"(p));
    return a;
}

#define SW128(o) ((o) ^ (((o) >> 3) & 0x70))

#define LDSM4(r0, r1, r2, r3, a) \
    asm volatile("ldmatrix.sync.aligned.m8n8.x4.shared.b16 {%0,%1,%2,%3}, [%4];" \
                 : "=r"(r0), "=r"(r1), "=r"(r2), "=r"(r3) : "r"(a))

#define MMA16816(d, a, b0, b1) \
    asm volatile("mma.sync.aligned.m16n8k16.row.col.f32.bf16.bf16.f32 " \
                 "{%0,%1,%2,%3}, {%4,%5,%6,%7}, {%8,%9}, {%0,%1,%2,%3};" \
                 : "+f"((d)[0]), "+f"((d)[1]), "+f"((d)[2]), "+f"((d)[3]) \
                 : "r"((a)[0]), "r"((a)[1]), "r"((a)[2]), "r"((a)[3]), \
                   "r"(b0), "r"(b1))

// ---------------------------------------------------------------------------
// Kernel 1: row norms + bf16 hi/lo split into K-concat arrays; zero accums.
// ---------------------------------------------------------------------------
__global__ void prep_kernel(const float* __restrict__ train,
                            const float* __restrict__ test) {
    int b = blockIdx.x, t = threadIdx.x;     // 256 threads, 1024 floats/row
    bool isTrain = b < TRAIN_N;
    const float* row = isTrain ? train + (size_t)b * KDIM
                               : test + (size_t)(b - TRAIN_N) * KDIM;
    float4 v = ((const float4*)row)[t];
    float s = v.x * v.x + v.y * v.y + v.z * v.z + v.w * v.w;
    #pragma unroll
    for (int o = 16; o; o >>= 1) s += __shfl_xor_sync(0xffffffffu, s, o);
    __shared__ float ws[8];
    __shared__ float s_inv;
    if ((t & 31) == 0) ws[t >> 5] = s;
    __syncthreads();
    if (t < 8) {
        float x = ws[t];
        #pragma unroll
        for (int o = 4; o; o >>= 1) x += __shfl_xor_sync(0xffu, x, o);
        if (t == 0) s_inv = rsqrtf(x);
    }
    __syncthreads();
    float inv = s_inv;

    float x0 = v.x * inv, x1 = v.y * inv, x2 = v.z * inv, x3 = v.w * inv;
    __nv_bfloat16 h0 = __float2bfloat16(x0), h1 = __float2bfloat16(x1);
    __nv_bfloat16 h2 = __float2bfloat16(x2), h3 = __float2bfloat16(x3);
    __nv_bfloat16 l0 = __float2bfloat16(x0 - __bfloat162float(h0));
    __nv_bfloat16 l1 = __float2bfloat16(x1 - __bfloat162float(h1));
    __nv_bfloat16 l2 = __float2bfloat16(x2 - __bfloat162float(h2));
    __nv_bfloat16 l3 = __float2bfloat16(x3 - __bfloat162float(h3));

    union { __nv_bfloat16 h[4]; uint2 u; } H, L;
    H.h[0] = h0; H.h[1] = h1; H.h[2] = h2; H.h[3] = h3;
    L.h[0] = l0; L.h[1] = l1; L.h[2] = l2; L.h[3] = l3;

    __nv_bfloat16* dst = isTrain ? g_B + (size_t)b * KSPLIT
                                 : g_A + (size_t)(b - TRAIN_N) * KSPLIT;
    uint2* d0 = (uint2*)dst + t;
    uint2* d1 = (uint2*)(dst + KDIM) + t;
    uint2* d2 = (uint2*)(dst + 2 * KDIM) + t;
    *d0 = H.u;                                   // seg0: hi (both)
    if (isTrain) { *d1 = L.u; *d2 = H.u; }       // B' = [hi, lo, hi]
    else         { *d1 = H.u; *d2 = L.u; }       // A' = [hi, hi, lo]

    if (!isTrain && t == 0) { g_tot[b - TRAIN_N] = 0.0f; g_s1[b - TRAIN_N] = 0.0f; }
}

// ---------------------------------------------------------------------------
// Kernel 2: HMMA GEMM + PNN epilogue.
// Dynamic SMEM: [0,1024) labels (256 f32); [1024, ...) STAGES x 48 KB tiles.
// ---------------------------------------------------------------------------
#define SMEM_TILE   1024
#define STAGE_BYTES (MT * 128 + NT * 128)   // 49152
#define B_OFF       (MT * 128)              // 16384
#define SMEM_TOTAL  (SMEM_TILE + STAGES * STAGE_BYTES)  // 197632

__device__ __forceinline__ void load_chunk(int tid, uint32_t sb, int stage,
                                           const char* gA, const char* gB,
                                           int chunk) {
    uint32_t base = sb + SMEM_TILE + stage * STAGE_BYTES;
    const char* srcA = gA + (size_t)chunk * 128;
    const char* srcB = gB + (size_t)chunk * 128;
    #pragma unroll
    for (int i = 0; i < 12; i++) {
        int u = tid + 256 * i;
        const char* src;
        uint32_t dst;
        if (u < 1024) {                 // A tile: 128 rows x 128 B
            int r = u >> 3, c = u & 7;
            src = srcA + (size_t)r * KPITCH + c * 16;
            dst = base + SW128((uint32_t)(r * 128 + c * 16));
        } else {                        // B tile: 256 rows x 128 B
            int vv = u - 1024;
            int r = vv >> 3, c = vv & 7;
            src = srcB + (size_t)r * KPITCH + c * 16;
            dst = base + B_OFF + SW128((uint32_t)(r * 128 + c * 16));
        }
        asm volatile("cp.async.cg.shared.global [%0], [%1], 16;" :: "r"(dst), "l"(src));
    }
    asm volatile("cp.async.commit_group;" ::: "memory");
}

__device__ __forceinline__ void compute_chunk(
    uint32_t aRowAddr, uint32_t aHi, uint32_t aXor,
    uint32_t bRowAddr, uint32_t bHi, uint32_t bXor,
    float (&acc)[4][8][4]) {
    #pragma unroll
    for (int ks = 0; ks < 4; ks++) {
        uint32_t aoff = ((uint32_t)(ks * 32) + aHi) ^ aXor;
        uint32_t boff = ((uint32_t)(ks * 32) + bHi) ^ bXor;
        uint32_t af[4][4], bq[4][4];
        #pragma unroll
        for (int mi = 0; mi < 4; mi++)
            LDSM4(af[mi][0], af[mi][1], af[mi][2], af[mi][3],
                  aRowAddr + mi * 2048 + aoff);
        #pragma unroll
        for (int nj = 0; nj < 4; nj++)
            LDSM4(bq[nj][0], bq[nj][1], bq[nj][2], bq[nj][3],
                  bRowAddr + nj * 2048 + boff);
        #pragma unroll
        for (int mi = 0; mi < 4; mi++) {
            #pragma unroll
            for (int nj = 0; nj < 4; nj++) {
                MMA16816(acc[mi][2 * nj],     af[mi], bq[nj][0], bq[nj][1]);
                MMA16816(acc[mi][2 * nj + 1], af[mi], bq[nj][2], bq[nj][3]);
            }
        }
    }
}

__global__ __launch_bounds__(256)
void pnn_mma(const int* __restrict__ label) {
    extern __shared__ __align__(1024) char smem[];
    uint32_t sb = smem_u32(smem);
    const int tid = threadIdx.x;
    const int wid = tid >> 5, lid = tid & 31;
    const int rowBase = blockIdx.y * MT;      // test rows
    const int colBase = blockIdx.x * NT;      // train rows

    float* slab = (float*)smem;
    slab[tid] = (float)label[colBase + tid];

    const char* gA = (const char*)g_A + (size_t)rowBase * KPITCH;
    const char* gB = (const char*)g_B + (size_t)colBase * KPITCH;

    // warp layout: 2 (m) x 4 (n)
    const int wm = (wid >> 2) * 64;
    const int wn = (wid & 3) * 64;

    // ldmatrix lane addressing (within stage, SW128: addr = r*128 + (c ^ ((r&7)<<4)))
    const int aRow = wm + (lid & 15);
    const uint32_t aXor = (uint32_t)((aRow & 7) << 4);
    const uint32_t aHi  = (uint32_t)(((lid >> 4) & 1) << 4);
    const int bRow = wn + (lid & 7) + (((lid >> 4) & 1) << 3);
    const uint32_t bXor = (uint32_t)((bRow & 7) << 4);
    const uint32_t bHi  = (uint32_t)(((lid >> 3) & 1) << 4);

    float acc[4][8][4];
    #pragma unroll
    for (int mi = 0; mi < 4; mi++)
        #pragma unroll
        for (int n = 0; n < 8; n++)
            #pragma unroll
            for (int c = 0; c < 4; c++) acc[mi][n][c] = 0.0f;

    #pragma unroll
    for (int s = 0; s < STAGES - 1; s++) load_chunk(tid, sb, s, gA, gB, s);

    #pragma unroll 1
    for (int t = 0; t < NCHUNK; t++) {
        asm volatile("cp.async.wait_group %0;" :: "n"(STAGES - 2) : "memory");
        __syncthreads();
        if (t + STAGES - 1 < NCHUNK) {
            load_chunk(tid, sb, (t + STAGES - 1) & (STAGES - 1), gA, gB,
                       t + STAGES - 1);
        } else {
            asm volatile("cp.async.commit_group;" ::: "memory");
        }
        uint32_t stageBase = sb + SMEM_TILE + (t & (STAGES - 1)) * STAGE_BYTES;
        compute_chunk(stageBase + (uint32_t)(aRow * 128), aHi, aXor,
                      stageBase + B_OFF + (uint32_t)(bRow * 128), bHi, bXor,
                      acc);
    }

    // ---- epilogue: dot -> distance -> Gauss -> class sums ----
    float labs[16];
    #pragma unroll
    for (int n8 = 0; n8 < 8; n8++) {
        labs[2 * n8]     = slab[wn + n8 * 8 + 2 * (lid & 3)];
        labs[2 * n8 + 1] = slab[wn + n8 * 8 + 2 * (lid & 3) + 1];
    }
    #pragma unroll
    for (int mi = 0; mi < 4; mi++) {
        float tA = 0.0f, sA = 0.0f, tB = 0.0f, sB = 0.0f;
        #pragma unroll
        for (int n8 = 0; n8 < 8; n8++) {
            #pragma unroll
            for (int j = 0; j < 2; j++) {
                float lab = labs[2 * n8 + j];
                {
                    float dot = acc[mi][n8][j];
                    float d2 = fmaxf(2.0f - 2.0f * dot, 0.0f);
                    float g = __expf(-2.0f * __fsqrt_rn(d2));
                    tA += g; sA += g * lab;
                }
                {
                    float dot = acc[mi][n8][2 + j];
                    float d2 = fmaxf(2.0f - 2.0f * dot, 0.0f);
                    float g = __expf(-2.0f * __fsqrt_rn(d2));
                    tB += g; sB += g * lab;
                }
            }
        }
        #pragma unroll
        for (int o = 1; o < 4; o <<= 1) {
            tA += __shfl_xor_sync(0xffffffffu, tA, o);
            sA += __shfl_xor_sync(0xffffffffu, sA, o);
            tB += __shfl_xor_sync(0xffffffffu, tB, o);
            sB += __shfl_xor_sync(0xffffffffu, sB, o);
        }
        if ((lid & 3) == 0) {
            int rowA = rowBase + wm + mi * 16 + (lid >> 2);
            atomicAdd(&g_tot[rowA], tA);
            atomicAdd(&g_s1[rowA], sA);
            atomicAdd(&g_tot[rowA + 8], tB);
            atomicAdd(&g_s1[rowA + 8], sB);
        }
    }
}

// ---------------------------------------------------------------------------
// Kernel 3: normalize probabilities, argmax, write output.
// ---------------------------------------------------------------------------
__global__ void finalize_kernel(float* __restrict__ out, int out_size) {
    int i = blockIdx.x * blockDim.x + threadIdx.x;
    if (i >= TEST_P) return;
    float tot = g_tot[i];
    float s1  = g_s1[i];
    float s0  = tot - s1;
    float p0  = s0 / tot;
    float p1  = s1 / tot;
    float res = (p1 > p0) ? 1.0f : 0.0f;
    if (out_size >= TEST_P * 3) {
        out[i] = res;
        out[TEST_P + 2 * i]     = p0;
        out[TEST_P + 2 * i + 1] = p1;
    } else if (out_size == TEST_P * 2) {
        out[2 * i]     = p0;
        out[2 * i + 1] = p1;
    } else {
        out[i] = res;
    }
}

extern "C" void kernel_launch(void* const* d_in, const int* in_sizes, int n_in,
                              void* d_out, int out_size) {
    const float* train = (const float*)d_in[0];
    const int*   label = (const int*)d_in[1];
    const float* test  = (const float*)d_in[2];

    cudaFuncSetAttribute(pnn_mma, cudaFuncAttributeMaxDynamicSharedMemorySize,
                         SMEM_TOTAL);

    prep_kernel<<<TRAIN_N + TEST_P, 256>>>(train, test);

    dim3 grid(TRAIN_N / NT, TEST_P / MT);   // (32, 32)
    pnn_mma<<<grid, 256, SMEM_TOTAL>>>(label);

    finalize_kernel<<<(TEST_P + 255) / 256, 256>>>((float*)d_out, out_size);
}

// round 5
// speedup vs baseline: 3.6406x; 1.1419x over previous
#include <cuda_runtime.h>
#include <cuda_bf16.h>
#include <cstdint>

// ---------------------------------------------------------------------------
// PNN_43095701848191 — mma.sync (HMMA) bf16x3-split, software-pipelined frags.
//   prep:  normalize rows, split x = hi + lo (bf16), K-concat:
//            A' = [hi, hi, lo]  (test,  4096 x 3072)
//            B' = [hi, lo, hi]  (train, 8192 x 3072)
//   gemm:  CTA tile 128x256 (8 warps, 64x64 warp tiles), K-chunks of 64,
//          SW128 swizzle, 4-stage cp.async pipeline, double-buffered
//          ldmatrix prefetch so LDSM latency hides under MMA issue.
//   epi:   g = exp(-2*sqrt(max(2-2*dot,0))), per-class row sums, atomics.
// ---------------------------------------------------------------------------

#define TRAIN_N 8192
#define TEST_P  4096
#define KDIM    1024
#define KSPLIT  3072
#define KPITCH  (KSPLIT * 2)      // bytes per row

#define MT 128
#define NT 256
#define KC 64
#define NCHUNK (KSPLIT / KC)      // 48
#define STAGES 4

__device__ __align__(16) __nv_bfloat16 g_A[TEST_P * KSPLIT];
__device__ __align__(16) __nv_bfloat16 g_B[TRAIN_N * KSPLIT];
__device__ float g_tot[TEST_P];
__device__ float g_s1[TEST_P];

__device__ __forceinline__ uint32_t smem_u32(const void* p) {
    uint32_t a;
    asm("{ .reg .u64 t; cvta.to.shared.u64 t, %1; cvt.u32.u64 %0, t; }"
        : "=r"(a) : "l"(p));
    return a;
}

#define SW128(o) ((o) ^ (((o) >> 3) & 0x70))

#define LDSM4(r0, r1, r2, r3, a) \
    asm volatile("ldmatrix.sync.aligned.m8n8.x4.shared.b16 {%0,%1,%2,%3}, [%4];" \
                 : "=r"(r0), "=r"(r1), "=r"(r2), "=r"(r3) : "r"(a))

#define MMA16816(d, a, b0, b1) \
    asm volatile("mma.sync.aligned.m16n8k16.row.col.f32.bf16.bf16.f32 " \
                 "{%0,%1,%2,%3}, {%4,%5,%6,%7}, {%8,%9}, {%0,%1,%2,%3};" \
                 : "+f"((d)[0]), "+f"((d)[1]), "+f"((d)[2]), "+f"((d)[3]) \
                 : "r"((a)[0]), "r"((a)[1]), "r"((a)[2]), "r"((a)[3]), \
                   "r"(b0), "r"(b1))

// ---------------------------------------------------------------------------
// Kernel 1: row norms + bf16 hi/lo split into K-concat arrays; zero accums.
// ---------------------------------------------------------------------------
__global__ void prep_kernel(const float* __restrict__ train,
                            const float* __restrict__ test) {
    int b = blockIdx.x, t = threadIdx.x;
    bool isTrain = b < TRAIN_N;
    const float* row = isTrain ? train + (size_t)b * KDIM
                               : test + (size_t)(b - TRAIN_N) * KDIM;
    float4 v = ((const float4*)row)[t];
    float s = v.x * v.x + v.y * v.y + v.z * v.z + v.w * v.w;
    #pragma unroll
    for (int o = 16; o; o >>= 1) s += __shfl_xor_sync(0xffffffffu, s, o);
    __shared__ float ws[8];
    __shared__ float s_inv;
    if ((t & 31) == 0) ws[t >> 5] = s;
    __syncthreads();
    if (t < 8) {
        float x = ws[t];
        #pragma unroll
        for (int o = 4; o; o >>= 1) x += __shfl_xor_sync(0xffu, x, o);
        if (t == 0) s_inv = rsqrtf(x);
    }
    __syncthreads();
    float inv = s_inv;

    float x0 = v.x * inv, x1 = v.y * inv, x2 = v.z * inv, x3 = v.w * inv;
    __nv_bfloat16 h0 = __float2bfloat16(x0), h1 = __float2bfloat16(x1);
    __nv_bfloat16 h2 = __float2bfloat16(x2), h3 = __float2bfloat16(x3);
    __nv_bfloat16 l0 = __float2bfloat16(x0 - __bfloat162float(h0));
    __nv_bfloat16 l1 = __float2bfloat16(x1 - __bfloat162float(h1));
    __nv_bfloat16 l2 = __float2bfloat16(x2 - __bfloat162float(h2));
    __nv_bfloat16 l3 = __float2bfloat16(x3 - __bfloat162float(h3));

    union { __nv_bfloat16 h[4]; uint2 u; } H, L;
    H.h[0] = h0; H.h[1] = h1; H.h[2] = h2; H.h[3] = h3;
    L.h[0] = l0; L.h[1] = l1; L.h[2] = l2; L.h[3] = l3;

    __nv_bfloat16* dst = isTrain ? g_B + (size_t)b * KSPLIT
                                 : g_A + (size_t)(b - TRAIN_N) * KSPLIT;
    uint2* d0 = (uint2*)dst + t;
    uint2* d1 = (uint2*)(dst + KDIM) + t;
    uint2* d2 = (uint2*)(dst + 2 * KDIM) + t;
    *d0 = H.u;
    if (isTrain) { *d1 = L.u; *d2 = H.u; }       // B' = [hi, lo, hi]
    else         { *d1 = H.u; *d2 = L.u; }       // A' = [hi, hi, lo]

    if (!isTrain && t == 0) { g_tot[b - TRAIN_N] = 0.0f; g_s1[b - TRAIN_N] = 0.0f; }
}

// ---------------------------------------------------------------------------
// Kernel 2: HMMA GEMM + PNN epilogue.
// ---------------------------------------------------------------------------
#define SMEM_TILE   1024
#define STAGE_BYTES (MT * 128 + NT * 128)   // 49152
#define B_OFF       (MT * 128)              // 16384
#define SMEM_TOTAL  (SMEM_TILE + STAGES * STAGE_BYTES)  // 197632

__device__ __forceinline__ void load_chunk(int tid, uint32_t sb, int stage,
                                           const char* gA, const char* gB,
                                           int chunk) {
    uint32_t base = sb + SMEM_TILE + stage * STAGE_BYTES;
    const char* srcA = gA + (size_t)chunk * 128;
    const char* srcB = gB + (size_t)chunk * 128;
    #pragma unroll
    for (int i = 0; i < 12; i++) {
        int u = tid + 256 * i;
        const char* src;
        uint32_t dst;
        if (u < 1024) {                 // A tile: 128 rows x 128 B
            int r = u >> 3, c = u & 7;
            src = srcA + (size_t)r * KPITCH + c * 16;
            dst = base + SW128((uint32_t)(r * 128 + c * 16));
        } else {                        // B tile: 256 rows x 128 B
            int vv = u - 1024;
            int r = vv >> 3, c = vv & 7;
            src = srcB + (size_t)r * KPITCH + c * 16;
            dst = base + B_OFF + SW128((uint32_t)(r * 128 + c * 16));
        }
        asm volatile("cp.async.cg.shared.global [%0], [%1], 16;" :: "r"(dst), "l"(src));
    }
    asm volatile("cp.async.commit_group;" ::: "memory");
}

// load one k16-step's fragments (4x A ldmatrix.x4 + 4x B ldmatrix.x4)
__device__ __forceinline__ void ld_frags(uint32_t (&fa)[4][4], uint32_t (&fb)[4][4],
                                         uint32_t stageBase, int ks,
                                         uint32_t aRowOff, uint32_t aHi, uint32_t aXor,
                                         uint32_t bRowOff, uint32_t bHi, uint32_t bXor) {
    uint32_t aoff = ((uint32_t)(ks * 32) + aHi) ^ aXor;
    uint32_t boff = ((uint32_t)(ks * 32) + bHi) ^ bXor;
    uint32_t aBase = stageBase + aRowOff;
    uint32_t bBase = stageBase + B_OFF + bRowOff;
    #pragma unroll
    for (int mi = 0; mi < 4; mi++)
        LDSM4(fa[mi][0], fa[mi][1], fa[mi][2], fa[mi][3], aBase + mi * 2048 + aoff);
    #pragma unroll
    for (int nj = 0; nj < 4; nj++)
        LDSM4(fb[nj][0], fb[nj][1], fb[nj][2], fb[nj][3], bBase + nj * 2048 + boff);
}

__device__ __forceinline__ void mma_step(const uint32_t (&fa)[4][4],
                                         const uint32_t (&fb)[4][4],
                                         float (&acc)[4][8][4]) {
    #pragma unroll
    for (int mi = 0; mi < 4; mi++) {
        #pragma unroll
        for (int nj = 0; nj < 4; nj++) {
            MMA16816(acc[mi][2 * nj],     fa[mi], fb[nj][0], fb[nj][1]);
            MMA16816(acc[mi][2 * nj + 1], fa[mi], fb[nj][2], fb[nj][3]);
        }
    }
}

__global__ __launch_bounds__(256)
void pnn_mma(const int* __restrict__ label) {
    extern __shared__ __align__(1024) char smem[];
    uint32_t sb = smem_u32(smem);
    const int tid = threadIdx.x;
    const int wid = tid >> 5, lid = tid & 31;
    const int rowBase = blockIdx.y * MT;      // test rows
    const int colBase = blockIdx.x * NT;      // train rows

    float* slab = (float*)smem;
    slab[tid] = (float)label[colBase + tid];

    const char* gA = (const char*)g_A + (size_t)rowBase * KPITCH;
    const char* gB = (const char*)g_B + (size_t)colBase * KPITCH;

    // warp layout: 2 (m) x 4 (n)
    const int wm = (wid >> 2) * 64;
    const int wn = (wid & 3) * 64;

    const int aRow = wm + (lid & 15);
    const uint32_t aXor = (uint32_t)((aRow & 7) << 4);
    const uint32_t aHi  = (uint32_t)(((lid >> 4) & 1) << 4);
    const uint32_t aRowOff = (uint32_t)(aRow * 128);
    const int bRow = wn + (lid & 7) + (((lid >> 4) & 1) << 3);
    const uint32_t bXor = (uint32_t)((bRow & 7) << 4);
    const uint32_t bHi  = (uint32_t)(((lid >> 3) & 1) << 4);
    const uint32_t bRowOff = (uint32_t)(bRow * 128);

    float acc[4][8][4];
    #pragma unroll
    for (int mi = 0; mi < 4; mi++)
        #pragma unroll
        for (int n = 0; n < 8; n++)
            #pragma unroll
            for (int c = 0; c < 4; c++) acc[mi][n][c] = 0.0f;

    // prologue: stage chunks 0..2; wait chunk 0; preload its ks0 fragments
    #pragma unroll
    for (int s = 0; s < STAGES - 1; s++) load_chunk(tid, sb, s, gA, gB, s);
    asm volatile("cp.async.wait_group %0;" :: "n"(STAGES - 2) : "memory");
    __syncthreads();

    uint32_t f0a[4][4], f0b[4][4], f1a[4][4], f1b[4][4];
    ld_frags(f0a, f0b, sb + SMEM_TILE, 0, aRowOff, aHi, aXor, bRowOff, bHi, bXor);

    #pragma unroll 1
    for (int t = 0; t < NCHUNK; t++) {
        const uint32_t base  = sb + SMEM_TILE + (t & (STAGES - 1)) * STAGE_BYTES;
        const uint32_t basen = sb + SMEM_TILE + ((t + 1) & (STAGES - 1)) * STAGE_BYTES;

        ld_frags(f1a, f1b, base, 1, aRowOff, aHi, aXor, bRowOff, bHi, bXor);
        mma_step(f0a, f0b, acc);
        ld_frags(f0a, f0b, base, 2, aRowOff, aHi, aXor, bRowOff, bHi, bXor);
        mma_step(f1a, f1b, acc);
        ld_frags(f1a, f1b, base, 3, aRowOff, aHi, aXor, bRowOff, bHi, bXor);
        mma_step(f0a, f0b, acc);

        // chunk boundary: make chunk t+1 visible, recycle stage (t-1)&3
        asm volatile("cp.async.wait_group %0;" :: "n"(STAGES - 2) : "memory");
        __syncthreads();
        if (t + STAGES - 1 < NCHUNK) {
            load_chunk(tid, sb, (t + STAGES - 1) & (STAGES - 1), gA, gB,
                       t + STAGES - 1);
        } else {
            asm volatile("cp.async.commit_group;" ::: "memory");
        }

        ld_frags(f0a, f0b, basen, 0, aRowOff, aHi, aXor, bRowOff, bHi, bXor);
        mma_step(f1a, f1b, acc);
    }

    // ---- epilogue: dot -> distance -> Gauss -> class sums ----
    float labs[16];
    #pragma unroll
    for (int n8 = 0; n8 < 8; n8++) {
        labs[2 * n8]     = slab[wn + n8 * 8 + 2 * (lid & 3)];
        labs[2 * n8 + 1] = slab[wn + n8 * 8 + 2 * (lid & 3) + 1];
    }
    #pragma unroll
    for (int mi = 0; mi < 4; mi++) {
        float tA = 0.0f, sA = 0.0f, tB = 0.0f, sB = 0.0f;
        #pragma unroll
        for (int n8 = 0; n8 < 8; n8++) {
            #pragma unroll
            for (int j = 0; j < 2; j++) {
                float lab = labs[2 * n8 + j];
                {
                    float dot = acc[mi][n8][j];
                    float d2 = fmaxf(2.0f - 2.0f * dot, 0.0f);
                    float g = __expf(-2.0f * __fsqrt_rn(d2));
                    tA += g; sA += g * lab;
                }
                {
                    float dot = acc[mi][n8][2 + j];
                    float d2 = fmaxf(2.0f - 2.0f * dot, 0.0f);
                    float g = __expf(-2.0f * __fsqrt_rn(d2));
                    tB += g; sB += g * lab;
                }
            }
        }
        #pragma unroll
        for (int o = 1; o < 4; o <<= 1) {
            tA += __shfl_xor_sync(0xffffffffu, tA, o);
            sA += __shfl_xor_sync(0xffffffffu, sA, o);
            tB += __shfl_xor_sync(0xffffffffu, tB, o);
            sB += __shfl_xor_sync(0xffffffffu, sB, o);
        }
        if ((lid & 3) == 0) {
            int rowA = rowBase + wm + mi * 16 + (lid >> 2);
            atomicAdd(&g_tot[rowA], tA);
            atomicAdd(&g_s1[rowA], sA);
            atomicAdd(&g_tot[rowA + 8], tB);
            atomicAdd(&g_s1[rowA + 8], sB);
        }
    }
}

// ---------------------------------------------------------------------------
// Kernel 3: normalize probabilities, argmax, write output.
// ---------------------------------------------------------------------------
__global__ void finalize_kernel(float* __restrict__ out, int out_size) {
    int i = blockIdx.x * blockDim.x + threadIdx.x;
    if (i >= TEST_P) return;
    float tot = g_tot[i];
    float s1  = g_s1[i];
    float s0  = tot - s1;
    float p0  = s0 / tot;
    float p1  = s1 / tot;
    float res = (p1 > p0) ? 1.0f : 0.0f;
    if (out_size >= TEST_P * 3) {
        out[i] = res;
        out[TEST_P + 2 * i]     = p0;
        out[TEST_P + 2 * i + 1] = p1;
    } else if (out_size == TEST_P * 2) {
        out[2 * i]     = p0;
        out[2 * i + 1] = p1;
    } else {
        out[i] = res;
    }
}

extern "C" void kernel_launch(void* const* d_in, const int* in_sizes, int n_in,
                              void* d_out, int out_size) {
    const float* train = (const float*)d_in[0];
    const int*   label = (const int*)d_in[1];
    const float* test  = (const float*)d_in[2];

    cudaFuncSetAttribute(pnn_mma, cudaFuncAttributeMaxDynamicSharedMemorySize,
                         SMEM_TOTAL);

    prep_kernel<<<TRAIN_N + TEST_P, 256>>>(train, test);

    dim3 grid(TRAIN_N / NT, TEST_P / MT);   // (32, 32)
    pnn_mma<<<grid, 256, SMEM_TOTAL>>>(label);

    finalize_kernel<<<(TEST_P + 255) / 256, 256>>>((float*)d_out, out_size);
}

// round 6
// speedup vs baseline: 3.7385x; 1.0269x over previous
#include <cuda_runtime.h>
#include <cuda_bf16.h>
#include <cstdint>

// ---------------------------------------------------------------------------
// PNN_43095701848191 — mma.sync (HMMA) bf16x3-split, superstage pipeline.
//   prep:  normalize rows, split x = hi + lo (bf16); store [hi, lo] (K=2048).
//   gemm:  logical K-concat A' = [hi,hi,lo], B' = [hi,lo,hi] realized by
//          chunk->source remap (srcA = c<16?c:c-16, srcB = c<32?c:c-32), so
//          dot = hi.hi + hi.lo + lo.hi  ~ fp32-accurate.
//          CTA tile 128x256 (8 warps, 64x64), 4 stages grouped as 2
//          superstages of 2 chunks: ONE wait_group+syncthreads per 2 chunks.
//          Double-buffered ldmatrix fragment prefetch throughout.
//   epi:   g = ex2(-2*log2e*sqrt(max(2-2*dot,0))), per-class sums, atomics.
// ---------------------------------------------------------------------------

#define TRAIN_N 8192
#define TEST_P  4096
#define KDIM    1024
#define KSTORE  2048
#define KPITCH  (KSTORE * 2)      // 4096 bytes per stored row

#define MT 128
#define NT 256
#define NCHUNK 48                 // logical K = 3072, 64 per chunk
#define NSS    (NCHUNK / 2)       // 24 superstages

__device__ __align__(16) __nv_bfloat16 g_A[TEST_P * KSTORE];
__device__ __align__(16) __nv_bfloat16 g_B[TRAIN_N * KSTORE];
__device__ float g_tot[TEST_P];
__device__ float g_s1[TEST_P];

__device__ __forceinline__ uint32_t smem_u32(const void* p) {
    uint32_t a;
    asm("{ .reg .u64 t; cvta.to.shared.u64 t, %1; cvt.u32.u64 %0, t; }"
        : "=r"(a) : "l"(p));
    return a;
}

#define SW128(o) ((o) ^ (((o) >> 3) & 0x70))

#define LDSM4(r0, r1, r2, r3, a) \
    asm volatile("ldmatrix.sync.aligned.m8n8.x4.shared.b16 {%0,%1,%2,%3}, [%4];" \
                 : "=r"(r0), "=r"(r1), "=r"(r2), "=r"(r3) : "r"(a))

#define MMA16816(d, a, b0, b1) \
    asm volatile("mma.sync.aligned.m16n8k16.row.col.f32.bf16.bf16.f32 " \
                 "{%0,%1,%2,%3}, {%4,%5,%6,%7}, {%8,%9}, {%0,%1,%2,%3};" \
                 : "+f"((d)[0]), "+f"((d)[1]), "+f"((d)[2]), "+f"((d)[3]) \
                 : "r"((a)[0]), "r"((a)[1]), "r"((a)[2]), "r"((a)[3]), \
                   "r"(b0), "r"(b1))

#define EX2(out, in) asm("ex2.approx.f32 %0, %1;" : "=f"(out) : "f"(in))

// ---------------------------------------------------------------------------
// Kernel 1: row norms + bf16 hi/lo split (store [hi, lo]); zero accumulators.
// ---------------------------------------------------------------------------
__global__ void prep_kernel(const float* __restrict__ train,
                            const float* __restrict__ test) {
    int b = blockIdx.x, t = threadIdx.x;
    bool isTrain = b < TRAIN_N;
    const float* row = isTrain ? train + (size_t)b * KDIM
                               : test + (size_t)(b - TRAIN_N) * KDIM;
    float4 v = ((const float4*)row)[t];
    float s = v.x * v.x + v.y * v.y + v.z * v.z + v.w * v.w;
    #pragma unroll
    for (int o = 16; o; o >>= 1) s += __shfl_xor_sync(0xffffffffu, s, o);
    __shared__ float ws[8];
    __shared__ float s_inv;
    if ((t & 31) == 0) ws[t >> 5] = s;
    __syncthreads();
    if (t < 8) {
        float x = ws[t];
        #pragma unroll
        for (int o = 4; o; o >>= 1) x += __shfl_xor_sync(0xffu, x, o);
        if (t == 0) s_inv = rsqrtf(x);
    }
    __syncthreads();
    float inv = s_inv;

    float x0 = v.x * inv, x1 = v.y * inv, x2 = v.z * inv, x3 = v.w * inv;
    __nv_bfloat16 h0 = __float2bfloat16(x0), h1 = __float2bfloat16(x1);
    __nv_bfloat16 h2 = __float2bfloat16(x2), h3 = __float2bfloat16(x3);
    __nv_bfloat16 l0 = __float2bfloat16(x0 - __bfloat162float(h0));
    __nv_bfloat16 l1 = __float2bfloat16(x1 - __bfloat162float(h1));
    __nv_bfloat16 l2 = __float2bfloat16(x2 - __bfloat162float(h2));
    __nv_bfloat16 l3 = __float2bfloat16(x3 - __bfloat162float(h3));

    union { __nv_bfloat16 h[4]; uint2 u; } H, L;
    H.h[0] = h0; H.h[1] = h1; H.h[2] = h2; H.h[3] = h3;
    L.h[0] = l0; L.h[1] = l1; L.h[2] = l2; L.h[3] = l3;

    __nv_bfloat16* dst = isTrain ? g_B + (size_t)b * KSTORE
                                 : g_A + (size_t)(b - TRAIN_N) * KSTORE;
    ((uint2*)dst)[t] = H.u;                // seg0: hi
    ((uint2*)(dst + KDIM))[t] = L.u;       // seg1: lo

    if (!isTrain && t == 0) { g_tot[b - TRAIN_N] = 0.0f; g_s1[b - TRAIN_N] = 0.0f; }
}

// ---------------------------------------------------------------------------
// Kernel 2: HMMA GEMM + PNN epilogue.
// ---------------------------------------------------------------------------
#define SMEM_TILE   1024
#define STAGE_BYTES (MT * 128 + NT * 128)   // 49152
#define B_OFF       (MT * 128)              // 16384
#define SMEM_TOTAL  (SMEM_TILE + 4 * STAGE_BYTES)  // 197632

// load one superstage (2 chunks) into stages {2*buf, 2*buf+1}; one commit.
__device__ __forceinline__ void load_ss(int tid, uint32_t sb, int buf,
                                        const char* gA, const char* gB, int ss) {
    #pragma unroll
    for (int h = 0; h < 2; h++) {
        int chunk = 2 * ss + h;
        int ca = (chunk < 16) ? chunk : chunk - 16;   // A' = [hi,hi,lo]
        int cb = (chunk < 32) ? chunk : chunk - 32;   // B' = [hi,lo,hi]
        uint32_t base = sb + SMEM_TILE + (uint32_t)(2 * buf + h) * STAGE_BYTES;
        const char* srcA = gA + (size_t)ca * 128;
        const char* srcB = gB + (size_t)cb * 128;
        #pragma unroll
        for (int i = 0; i < 12; i++) {
            int u = tid + 256 * i;
            const char* src;
            uint32_t dst;
            if (u < 1024) {                 // A tile: 128 rows x 128 B
                int r = u >> 3, c = u & 7;
                src = srcA + (size_t)r * KPITCH + c * 16;
                dst = base + SW128((uint32_t)(r * 128 + c * 16));
            } else {                        // B tile: 256 rows x 128 B
                int vv = u - 1024;
                int r = vv >> 3, c = vv & 7;
                src = srcB + (size_t)r * KPITCH + c * 16;
                dst = base + B_OFF + SW128((uint32_t)(r * 128 + c * 16));
            }
            asm volatile("cp.async.cg.shared.global [%0], [%1], 16;"
                         :: "r"(dst), "l"(src));
        }
    }
    asm volatile("cp.async.commit_group;" ::: "memory");
}

__device__ __forceinline__ void ld_frags(uint32_t (&fa)[4][4], uint32_t (&fb)[4][4],
                                         uint32_t stageBase, int ks,
                                         uint32_t aRowOff, uint32_t aHi, uint32_t aXor,
                                         uint32_t bRowOff, uint32_t bHi, uint32_t bXor) {
    uint32_t aoff = ((uint32_t)(ks * 32) + aHi) ^ aXor;
    uint32_t boff = ((uint32_t)(ks * 32) + bHi) ^ bXor;
    uint32_t aBase = stageBase + aRowOff;
    uint32_t bBase = stageBase + B_OFF + bRowOff;
    #pragma unroll
    for (int mi = 0; mi < 4; mi++)
        LDSM4(fa[mi][0], fa[mi][1], fa[mi][2], fa[mi][3], aBase + mi * 2048 + aoff);
    #pragma unroll
    for (int nj = 0; nj < 4; nj++)
        LDSM4(fb[nj][0], fb[nj][1], fb[nj][2], fb[nj][3], bBase + nj * 2048 + boff);
}

__device__ __forceinline__ void mma_step(const uint32_t (&fa)[4][4],
                                         const uint32_t (&fb)[4][4],
                                         float (&acc)[4][8][4]) {
    #pragma unroll
    for (int mi = 0; mi < 4; mi++) {
        #pragma unroll
        for (int nj = 0; nj < 4; nj++) {
            MMA16816(acc[mi][2 * nj],     fa[mi], fb[nj][0], fb[nj][1]);
            MMA16816(acc[mi][2 * nj + 1], fa[mi], fb[nj][2], fb[nj][3]);
        }
    }
}

__global__ __launch_bounds__(256)
void pnn_mma(const int* __restrict__ label) {
    extern __shared__ __align__(1024) char smem[];
    uint32_t sb = smem_u32(smem);
    const int tid = threadIdx.x;
    const int wid = tid >> 5, lid = tid & 31;
    const int rowBase = blockIdx.y * MT;      // test rows
    const int colBase = blockIdx.x * NT;      // train rows

    float* slab = (float*)smem;
    slab[tid] = (float)label[colBase + tid];

    const char* gA = (const char*)g_A + (size_t)rowBase * KPITCH;
    const char* gB = (const char*)g_B + (size_t)colBase * KPITCH;

    // warp layout: 2 (m) x 4 (n)
    const int wm = (wid >> 2) * 64;
    const int wn = (wid & 3) * 64;

    const int aRow = wm + (lid & 15);
    const uint32_t aXor = (uint32_t)((aRow & 7) << 4);
    const uint32_t aHi  = (uint32_t)(((lid >> 4) & 1) << 4);
    const uint32_t aRowOff = (uint32_t)(aRow * 128);
    const int bRow = wn + (lid & 7) + (((lid >> 4) & 1) << 3);
    const uint32_t bXor = (uint32_t)((bRow & 7) << 4);
    const uint32_t bHi  = (uint32_t)(((lid >> 3) & 1) << 4);
    const uint32_t bRowOff = (uint32_t)(bRow * 128);

    float acc[4][8][4];
    #pragma unroll
    for (int mi = 0; mi < 4; mi++)
        #pragma unroll
        for (int n = 0; n < 8; n++)
            #pragma unroll
            for (int c = 0; c < 4; c++) acc[mi][n][c] = 0.0f;

    // prologue: SS0 -> buf0, SS1 -> buf1; wait SS0; preload its ks0 frags.
    load_ss(tid, sb, 0, gA, gB, 0);
    load_ss(tid, sb, 1, gA, gB, 1);
    asm volatile("cp.async.wait_group 1;" ::: "memory");
    __syncthreads();

    uint32_t f0a[4][4], f0b[4][4], f1a[4][4], f1b[4][4];
    ld_frags(f0a, f0b, sb + SMEM_TILE, 0, aRowOff, aHi, aXor, bRowOff, bHi, bXor);

    #pragma unroll 1
    for (int c = 0; c < NSS; c++) {
        const int buf = c & 1;
        const uint32_t s0 = sb + SMEM_TILE + (uint32_t)(2 * buf) * STAGE_BYTES;
        const uint32_t s1 = s0 + STAGE_BYTES;
        const uint32_t sn = sb + SMEM_TILE + (uint32_t)(2 * ((c + 1) & 1)) * STAGE_BYTES;

        // 8 k-steps (2 chunks), fragment double-buffered
        ld_frags(f1a, f1b, s0, 1, aRowOff, aHi, aXor, bRowOff, bHi, bXor);
        mma_step(f0a, f0b, acc);
        ld_frags(f0a, f0b, s0, 2, aRowOff, aHi, aXor, bRowOff, bHi, bXor);
        mma_step(f1a, f1b, acc);
        ld_frags(f1a, f1b, s0, 3, aRowOff, aHi, aXor, bRowOff, bHi, bXor);
        mma_step(f0a, f0b, acc);
        ld_frags(f0a, f0b, s1, 0, aRowOff, aHi, aXor, bRowOff, bHi, bXor);
        mma_step(f1a, f1b, acc);
        ld_frags(f1a, f1b, s1, 1, aRowOff, aHi, aXor, bRowOff, bHi, bXor);
        mma_step(f0a, f0b, acc);
        ld_frags(f0a, f0b, s1, 2, aRowOff, aHi, aXor, bRowOff, bHi, bXor);
        mma_step(f1a, f1b, acc);
        ld_frags(f1a, f1b, s1, 3, aRowOff, aHi, aXor, bRowOff, bHi, bXor);
        mma_step(f0a, f0b, acc);

        // superstage boundary: publish SS(c+1), recycle buf for SS(c+2)
        asm volatile("cp.async.wait_group 0;" ::: "memory");
        __syncthreads();
        if (c + 2 < NSS) load_ss(tid, sb, buf, gA, gB, c + 2);
        if (c + 1 < NSS)
            ld_frags(f0a, f0b, sn, 0, aRowOff, aHi, aXor, bRowOff, bHi, bXor);
        mma_step(f1a, f1b, acc);
    }

    // ---- epilogue: dot -> distance -> Gauss -> class sums ----
    const float C = -2.885390082f;   // -2 * log2(e)
    float labs[16];
    #pragma unroll
    for (int n8 = 0; n8 < 8; n8++) {
        labs[2 * n8]     = slab[wn + n8 * 8 + 2 * (lid & 3)];
        labs[2 * n8 + 1] = slab[wn + n8 * 8 + 2 * (lid & 3) + 1];
    }
    #pragma unroll
    for (int mi = 0; mi < 4; mi++) {
        float tA = 0.0f, sA = 0.0f, tB = 0.0f, sB = 0.0f;
        #pragma unroll
        for (int n8 = 0; n8 < 8; n8++) {
            #pragma unroll
            for (int j = 0; j < 2; j++) {
                float lab = labs[2 * n8 + j];
                {
                    float d2 = fmaxf(2.0f - 2.0f * acc[mi][n8][j], 0.0f);
                    float d;
                    asm("sqrt.approx.f32 %0, %1;" : "=f"(d) : "f"(d2));
                    float g; EX2(g, C * d);
                    tA += g; sA += g * lab;
                }
                {
                    float d2 = fmaxf(2.0f - 2.0f * acc[mi][n8][2 + j], 0.0f);
                    float d;
                    asm("sqrt.approx.f32 %0, %1;" : "=f"(d) : "f"(d2));
                    float g; EX2(g, C * d);
                    tB += g; sB += g * lab;
                }
            }
        }
        #pragma unroll
        for (int o = 1; o < 4; o <<= 1) {
            tA += __shfl_xor_sync(0xffffffffu, tA, o);
            sA += __shfl_xor_sync(0xffffffffu, sA, o);
            tB += __shfl_xor_sync(0xffffffffu, tB, o);
            sB += __shfl_xor_sync(0xffffffffu, sB, o);
        }
        if ((lid & 3) == 0) {
            int rowA = rowBase + wm + mi * 16 + (lid >> 2);
            atomicAdd(&g_tot[rowA], tA);
            atomicAdd(&g_s1[rowA], sA);
            atomicAdd(&g_tot[rowA + 8], tB);
            atomicAdd(&g_s1[rowA + 8], sB);
        }
    }
}

// ---------------------------------------------------------------------------
// Kernel 3: normalize probabilities, argmax, write output.
// ---------------------------------------------------------------------------
__global__ void finalize_kernel(float* __restrict__ out, int out_size) {
    int i = blockIdx.x * blockDim.x + threadIdx.x;
    if (i >= TEST_P) return;
    float tot = g_tot[i];
    float s1  = g_s1[i];
    float s0  = tot - s1;
    float p0  = s0 / tot;
    float p1  = s1 / tot;
    float res = (p1 > p0) ? 1.0f : 0.0f;
    if (out_size >= TEST_P * 3) {
        out[i] = res;
        out[TEST_P + 2 * i]     = p0;
        out[TEST_P + 2 * i + 1] = p1;
    } else if (out_size == TEST_P * 2) {
        out[2 * i]     = p0;
        out[2 * i + 1] = p1;
    } else {
        out[i] = res;
    }
}

extern "C" void kernel_launch(void* const* d_in, const int* in_sizes, int n_in,
                              void* d_out, int out_size) {
    const float* train = (const float*)d_in[0];
    const int*   label = (const int*)d_in[1];
    const float* test  = (const float*)d_in[2];

    cudaFuncSetAttribute(pnn_mma, cudaFuncAttributeMaxDynamicSharedMemorySize,
                         SMEM_TOTAL);

    prep_kernel<<<TRAIN_N + TEST_P, 256>>>(train, test);

    dim3 grid(TRAIN_N / NT, TEST_P / MT);   // (32, 32)
    pnn_mma<<<grid, 256, SMEM_TOTAL>>>(label);

    finalize_kernel<<<(TEST_P + 255) / 256, 256>>>((float*)d_out, out_size);
}

// round 7
// speedup vs baseline: 9.8700x; 2.6401x over previous
#include <cuda_runtime.h>
#include <cuda_fp16.h>
#include <cstdint>

// ---------------------------------------------------------------------------
// PNN_43095701848191 — fp16 HMMA GEMM (K=1024) + exact fp32 fixup for rows
// whose class-probability gap is within 52 sigma of the fp16 noise floor.
//
//   prep:    row L2 norms; store normalized rows as fp16 (A: test, B: train);
//            store inverse norms for the fixup path; zero accumulators.
//   gemm:    CTA tile 128x256 (8 warps, 64x64 warp tiles), K-chunks of 64,
//            SW128 swizzle, 4 stages as 2 superstages (one wait+sync per 2
//            chunks), double-buffered ldmatrix fragments,
//            mma.sync.m16n8k16.f32.f16.f16.f32. Epilogue: Gauss + class sums.
//   final:   probs + argmax; flag rows with |p1-p0| < 1e-5 into a compact
//            list (fp16 noise on the gap ~ 1.9e-7, so unflagged rows cannot
//            flip); zero per-row fixup accumulators.
//   fixup:   persistent worker blocks recompute flagged rows' 8192 dots in
//            exact fp32 (same math class as the reference), then overwrite
//            those rows' outputs.
// ---------------------------------------------------------------------------

#define TRAIN_N 8192
#define TEST_P  4096
#define KDIM    1024
#define KPITCH  (KDIM * 2)        // 2048 bytes per fp16 row

#define MT 128
#define NT 256
#define NCHUNK (KDIM / 64)        // 16
#define NSS    (NCHUNK / 2)       // 8 superstages

#define NSLICE  32                // fixup: train slices per flagged row
#define FIX_TAU 1e-5f

__device__ __align__(16) __half g_A[TEST_P * KDIM];
__device__ __align__(16) __half g_B[TRAIN_N * KDIM];
__device__ float g_tot[TEST_P];
__device__ float g_s1[TEST_P];
__device__ float g_invte[TEST_P];
__device__ float g_invtr[TRAIN_N];
__device__ int   g_flagged[TEST_P];
__device__ int   g_flaglist[TEST_P];
__device__ int   g_flagcount;
__device__ float g_ftot[TEST_P];
__device__ float g_fs1[TEST_P];

__device__ __forceinline__ uint32_t smem_u32(const void* p) {
    uint32_t a;
    asm("{ .reg .u64 t; cvta.to.shared.u64 t, %1; cvt.u32.u64 %0, t; }"
        : "=r"(a) : "l"(p));
    return a;
}

#define SW128(o) ((o) ^ (((o) >> 3) & 0x70))

#define LDSM4(r0, r1, r2, r3, a) \
    asm volatile("ldmatrix.sync.aligned.m8n8.x4.shared.b16 {%0,%1,%2,%3}, [%4];" \
                 : "=r"(r0), "=r"(r1), "=r"(r2), "=r"(r3) : "r"(a))

#define MMA16816(d, a, b0, b1) \
    asm volatile("mma.sync.aligned.m16n8k16.row.col.f32.f16.f16.f32 " \
                 "{%0,%1,%2,%3}, {%4,%5,%6,%7}, {%8,%9}, {%0,%1,%2,%3};" \
                 : "+f"((d)[0]), "+f"((d)[1]), "+f"((d)[2]), "+f"((d)[3]) \
                 : "r"((a)[0]), "r"((a)[1]), "r"((a)[2]), "r"((a)[3]), \
                   "r"(b0), "r"(b1))

#define EX2(out, in) asm("ex2.approx.f32 %0, %1;" : "=f"(out) : "f"(in))

// ---------------------------------------------------------------------------
// Kernel 1: row norms; normalized fp16 rows; inverse norms; zero accums.
// ---------------------------------------------------------------------------
__global__ void prep_kernel(const float* __restrict__ train,
                            const float* __restrict__ test) {
    int b = blockIdx.x, t = threadIdx.x;     // 256 threads, 1024 floats/row
    bool isTrain = b < TRAIN_N;
    const float* row = isTrain ? train + (size_t)b * KDIM
                               : test + (size_t)(b - TRAIN_N) * KDIM;
    float4 v = ((const float4*)row)[t];
    float s = v.x * v.x + v.y * v.y + v.z * v.z + v.w * v.w;
    #pragma unroll
    for (int o = 16; o; o >>= 1) s += __shfl_xor_sync(0xffffffffu, s, o);
    __shared__ float ws[8];
    __shared__ float s_inv;
    if ((t & 31) == 0) ws[t >> 5] = s;
    __syncthreads();
    if (t < 8) {
        float x = ws[t];
        #pragma unroll
        for (int o = 4; o; o >>= 1) x += __shfl_xor_sync(0xffu, x, o);
        if (t == 0) s_inv = rsqrtf(x);
    }
    __syncthreads();
    float inv = s_inv;

    union { __half h[4]; uint2 u; } H;
    H.h[0] = __float2half_rn(v.x * inv);
    H.h[1] = __float2half_rn(v.y * inv);
    H.h[2] = __float2half_rn(v.z * inv);
    H.h[3] = __float2half_rn(v.w * inv);

    __half* dst = isTrain ? g_B + (size_t)b * KDIM
                          : g_A + (size_t)(b - TRAIN_N) * KDIM;
    ((uint2*)dst)[t] = H.u;

    if (t == 0) {
        if (isTrain) {
            g_invtr[b] = inv;
        } else {
            g_invte[b - TRAIN_N] = inv;
            g_tot[b - TRAIN_N] = 0.0f;
            g_s1[b - TRAIN_N] = 0.0f;
        }
        if (b == 0) g_flagcount = 0;
    }
}

// ---------------------------------------------------------------------------
// Kernel 2: HMMA GEMM + PNN epilogue.
// ---------------------------------------------------------------------------
#define SMEM_TILE   1024
#define STAGE_BYTES (MT * 128 + NT * 128)   // 49152
#define B_OFF       (MT * 128)              // 16384
#define SMEM_TOTAL  (SMEM_TILE + 4 * STAGE_BYTES)  // 197632

// load one superstage (2 chunks) into stages {2*buf, 2*buf+1}; one commit.
__device__ __forceinline__ void load_ss(int tid, uint32_t sb, int buf,
                                        const char* gA, const char* gB, int ss) {
    #pragma unroll
    for (int h = 0; h < 2; h++) {
        int chunk = 2 * ss + h;
        uint32_t base = sb + SMEM_TILE + (uint32_t)(2 * buf + h) * STAGE_BYTES;
        const char* srcA = gA + (size_t)chunk * 128;
        const char* srcB = gB + (size_t)chunk * 128;
        #pragma unroll
        for (int i = 0; i < 12; i++) {
            int u = tid + 256 * i;
            const char* src;
            uint32_t dst;
            if (u < 1024) {                 // A tile: 128 rows x 128 B
                int r = u >> 3, c = u & 7;
                src = srcA + (size_t)r * KPITCH + c * 16;
                dst = base + SW128((uint32_t)(r * 128 + c * 16));
            } else {                        // B tile: 256 rows x 128 B
                int vv = u - 1024;
                int r = vv >> 3, c = vv & 7;
                src = srcB + (size_t)r * KPITCH + c * 16;
                dst = base + B_OFF + SW128((uint32_t)(r * 128 + c * 16));
            }
            asm volatile("cp.async.cg.shared.global [%0], [%1], 16;"
                         :: "r"(dst), "l"(src));
        }
    }
    asm volatile("cp.async.commit_group;" ::: "memory");
}

__device__ __forceinline__ void ld_frags(uint32_t (&fa)[4][4], uint32_t (&fb)[4][4],
                                         uint32_t stageBase, int ks,
                                         uint32_t aRowOff, uint32_t aHi, uint32_t aXor,
                                         uint32_t bRowOff, uint32_t bHi, uint32_t bXor) {
    uint32_t aoff = ((uint32_t)(ks * 32) + aHi) ^ aXor;
    uint32_t boff = ((uint32_t)(ks * 32) + bHi) ^ bXor;
    uint32_t aBase = stageBase + aRowOff;
    uint32_t bBase = stageBase + B_OFF + bRowOff;
    #pragma unroll
    for (int mi = 0; mi < 4; mi++)
        LDSM4(fa[mi][0], fa[mi][1], fa[mi][2], fa[mi][3], aBase + mi * 2048 + aoff);
    #pragma unroll
    for (int nj = 0; nj < 4; nj++)
        LDSM4(fb[nj][0], fb[nj][1], fb[nj][2], fb[nj][3], bBase + nj * 2048 + boff);
}

__device__ __forceinline__ void mma_step(const uint32_t (&fa)[4][4],
                                         const uint32_t (&fb)[4][4],
                                         float (&acc)[4][8][4]) {
    #pragma unroll
    for (int mi = 0; mi < 4; mi++) {
        #pragma unroll
        for (int nj = 0; nj < 4; nj++) {
            MMA16816(acc[mi][2 * nj],     fa[mi], fb[nj][0], fb[nj][1]);
            MMA16816(acc[mi][2 * nj + 1], fa[mi], fb[nj][2], fb[nj][3]);
        }
    }
}

__global__ __launch_bounds__(256)
void pnn_mma(const int* __restrict__ label) {
    extern __shared__ __align__(1024) char smem[];
    uint32_t sb = smem_u32(smem);
    const int tid = threadIdx.x;
    const int wid = tid >> 5, lid = tid & 31;
    const int rowBase = blockIdx.y * MT;      // test rows
    const int colBase = blockIdx.x * NT;      // train rows

    float* slab = (float*)smem;
    slab[tid] = (float)label[colBase + tid];

    const char* gA = (const char*)g_A + (size_t)rowBase * KPITCH;
    const char* gB = (const char*)g_B + (size_t)colBase * KPITCH;

    // warp layout: 2 (m) x 4 (n)
    const int wm = (wid >> 2) * 64;
    const int wn = (wid & 3) * 64;

    const int aRow = wm + (lid & 15);
    const uint32_t aXor = (uint32_t)((aRow & 7) << 4);
    const uint32_t aHi  = (uint32_t)(((lid >> 4) & 1) << 4);
    const uint32_t aRowOff = (uint32_t)(aRow * 128);
    const int bRow = wn + (lid & 7) + (((lid >> 4) & 1) << 3);
    const uint32_t bXor = (uint32_t)((bRow & 7) << 4);
    const uint32_t bHi  = (uint32_t)(((lid >> 3) & 1) << 4);
    const uint32_t bRowOff = (uint32_t)(bRow * 128);

    float acc[4][8][4];
    #pragma unroll
    for (int mi = 0; mi < 4; mi++)
        #pragma unroll
        for (int n = 0; n < 8; n++)
            #pragma unroll
            for (int c = 0; c < 4; c++) acc[mi][n][c] = 0.0f;

    // prologue: SS0 -> buf0, SS1 -> buf1; wait SS0; preload its ks0 frags.
    load_ss(tid, sb, 0, gA, gB, 0);
    load_ss(tid, sb, 1, gA, gB, 1);
    asm volatile("cp.async.wait_group 1;" ::: "memory");
    __syncthreads();

    uint32_t f0a[4][4], f0b[4][4], f1a[4][4], f1b[4][4];
    ld_frags(f0a, f0b, sb + SMEM_TILE, 0, aRowOff, aHi, aXor, bRowOff, bHi, bXor);

    #pragma unroll 1
    for (int c = 0; c < NSS; c++) {
        const int buf = c & 1;
        const uint32_t s0 = sb + SMEM_TILE + (uint32_t)(2 * buf) * STAGE_BYTES;
        const uint32_t s1 = s0 + STAGE_BYTES;
        const uint32_t sn = sb + SMEM_TILE + (uint32_t)(2 * ((c + 1) & 1)) * STAGE_BYTES;

        ld_frags(f1a, f1b, s0, 1, aRowOff, aHi, aXor, bRowOff, bHi, bXor);
        mma_step(f0a, f0b, acc);
        ld_frags(f0a, f0b, s0, 2, aRowOff, aHi, aXor, bRowOff, bHi, bXor);
        mma_step(f1a, f1b, acc);
        ld_frags(f1a, f1b, s0, 3, aRowOff, aHi, aXor, bRowOff, bHi, bXor);
        mma_step(f0a, f0b, acc);
        ld_frags(f0a, f0b, s1, 0, aRowOff, aHi, aXor, bRowOff, bHi, bXor);
        mma_step(f1a, f1b, acc);
        ld_frags(f1a, f1b, s1, 1, aRowOff, aHi, aXor, bRowOff, bHi, bXor);
        mma_step(f0a, f0b, acc);
        ld_frags(f0a, f0b, s1, 2, aRowOff, aHi, aXor, bRowOff, bHi, bXor);
        mma_step(f1a, f1b, acc);
        ld_frags(f1a, f1b, s1, 3, aRowOff, aHi, aXor, bRowOff, bHi, bXor);
        mma_step(f0a, f0b, acc);

        asm volatile("cp.async.wait_group 0;" ::: "memory");
        __syncthreads();
        if (c + 2 < NSS) load_ss(tid, sb, buf, gA, gB, c + 2);
        if (c + 1 < NSS)
            ld_frags(f0a, f0b, sn, 0, aRowOff, aHi, aXor, bRowOff, bHi, bXor);
        mma_step(f1a, f1b, acc);
    }

    // ---- epilogue: dot -> distance -> Gauss -> class sums ----
    const float C = -2.885390082f;   // -2 * log2(e)
    float labs[16];
    #pragma unroll
    for (int n8 = 0; n8 < 8; n8++) {
        labs[2 * n8]     = slab[wn + n8 * 8 + 2 * (lid & 3)];
        labs[2 * n8 + 1] = slab[wn + n8 * 8 + 2 * (lid & 3) + 1];
    }
    #pragma unroll
    for (int mi = 0; mi < 4; mi++) {
        float tA = 0.0f, sA = 0.0f, tB = 0.0f, sB = 0.0f;
        #pragma unroll
        for (int n8 = 0; n8 < 8; n8++) {
            #pragma unroll
            for (int j = 0; j < 2; j++) {
                float lab = labs[2 * n8 + j];
                {
                    float d2 = fmaxf(2.0f - 2.0f * acc[mi][n8][j], 0.0f);
                    float d;
                    asm("sqrt.approx.f32 %0, %1;" : "=f"(d) : "f"(d2));
                    float g; EX2(g, C * d);
                    tA += g; sA += g * lab;
                }
                {
                    float d2 = fmaxf(2.0f - 2.0f * acc[mi][n8][2 + j], 0.0f);
                    float d;
                    asm("sqrt.approx.f32 %0, %1;" : "=f"(d) : "f"(d2));
                    float g; EX2(g, C * d);
                    tB += g; sB += g * lab;
                }
            }
        }
        #pragma unroll
        for (int o = 1; o < 4; o <<= 1) {
            tA += __shfl_xor_sync(0xffffffffu, tA, o);
            sA += __shfl_xor_sync(0xffffffffu, sA, o);
            tB += __shfl_xor_sync(0xffffffffu, tB, o);
            sB += __shfl_xor_sync(0xffffffffu, sB, o);
        }
        if ((lid & 3) == 0) {
            int rowA = rowBase + wm + mi * 16 + (lid >> 2);
            atomicAdd(&g_tot[rowA], tA);
            atomicAdd(&g_s1[rowA], sA);
            atomicAdd(&g_tot[rowA + 8], tB);
            atomicAdd(&g_s1[rowA + 8], sB);
        }
    }
}

// ---------------------------------------------------------------------------
// Kernel 3: probs + argmax + write; flag near-tie rows for exact fixup.
// ---------------------------------------------------------------------------
__global__ void finalize_kernel(float* __restrict__ out, int out_size) {
    int i = blockIdx.x * blockDim.x + threadIdx.x;
    if (i >= TEST_P) return;
    float tot = g_tot[i];
    float s1  = g_s1[i];
    float s0  = tot - s1;
    float p0  = s0 / tot;
    float p1  = s1 / tot;
    float res = (p1 > p0) ? 1.0f : 0.0f;
    if (out_size >= TEST_P * 3) {
        out[i] = res;
        out[TEST_P + 2 * i]     = p0;
        out[TEST_P + 2 * i + 1] = p1;
    } else if (out_size == TEST_P * 2) {
        out[2 * i]     = p0;
        out[2 * i + 1] = p1;
    } else {
        out[i] = res;
    }
    int fl = (fabsf(p1 - p0) < FIX_TAU) ? 1 : 0;
    g_flagged[i] = fl;
    g_ftot[i] = 0.0f;
    g_fs1[i]  = 0.0f;
    if (fl) {
        int idx = atomicAdd(&g_flagcount, 1);
        g_flaglist[idx] = i;
    }
}

// ---------------------------------------------------------------------------
// Kernel 4: exact fp32 recompute for flagged rows (persistent workers).
// Work item = (flagged row, train slice of 256 rows).
// ---------------------------------------------------------------------------
__global__ void fixup_accum(const float* __restrict__ train,
                            const float* __restrict__ test,
                            const int* __restrict__ label) {
    __shared__ float sa[KDIM];
    int total = g_flagcount * NSLICE;
    for (int w = blockIdx.x; w < total; w += gridDim.x) {
        int row   = g_flaglist[w / NSLICE];
        int slice = w % NSLICE;
        float ivte = g_invte[row];
        for (int i = threadIdx.x; i < KDIM; i += 256)
            sa[i] = test[(size_t)row * KDIM + i] * ivte;
        __syncthreads();
        int wid = threadIdx.x >> 5, lid = threadIdx.x & 31;
        float tot = 0.0f, s1 = 0.0f;
        for (int r = 0; r < 32; r++) {
            int trow = slice * 256 + wid * 32 + r;
            const float* brow = train + (size_t)trow * KDIM;
            float d = 0.0f;
            #pragma unroll 8
            for (int i = lid; i < KDIM; i += 32) d += sa[i] * brow[i];
            #pragma unroll
            for (int o = 16; o; o >>= 1) d += __shfl_xor_sync(0xffffffffu, d, o);
            if (lid == 0) {
                float dot = d * g_invtr[trow];
                float d2 = fmaxf(2.0f - 2.0f * dot, 0.0f);
                float g = __expf(-2.0f * sqrtf(d2));
                tot += g;
                s1  += g * (float)label[trow];
            }
        }
        if (lid == 0) {
            atomicAdd(&g_ftot[row], tot);
            atomicAdd(&g_fs1[row], s1);
        }
        __syncthreads();
    }
}

// ---------------------------------------------------------------------------
// Kernel 5: overwrite flagged rows' outputs with the exact values.
// ---------------------------------------------------------------------------
__global__ void fixup_write(float* __restrict__ out, int out_size) {
    int i = blockIdx.x * blockDim.x + threadIdx.x;
    if (i >= TEST_P || !g_flagged[i]) return;
    float tot = g_ftot[i];
    float s1  = g_fs1[i];
    float s0  = tot - s1;
    float p0  = s0 / tot;
    float p1  = s1 / tot;
    float res = (p1 > p0) ? 1.0f : 0.0f;
    if (out_size >= TEST_P * 3) {
        out[i] = res;
        out[TEST_P + 2 * i]     = p0;
        out[TEST_P + 2 * i + 1] = p1;
    } else if (out_size == TEST_P * 2) {
        out[2 * i]     = p0;
        out[2 * i + 1] = p1;
    } else {
        out[i] = res;
    }
}

extern "C" void kernel_launch(void* const* d_in, const int* in_sizes, int n_in,
                              void* d_out, int out_size) {
    const float* train = (const float*)d_in[0];
    const int*   label = (const int*)d_in[1];
    const float* test  = (const float*)d_in[2];

    cudaFuncSetAttribute(pnn_mma, cudaFuncAttributeMaxDynamicSharedMemorySize,
                         SMEM_TOTAL);

    prep_kernel<<<TRAIN_N + TEST_P, 256>>>(train, test);

    dim3 grid(TRAIN_N / NT, TEST_P / MT);   // (32, 32)
    pnn_mma<<<grid, 256, SMEM_TOTAL>>>(label);

    finalize_kernel<<<(TEST_P + 255) / 256, 256>>>((float*)d_out, out_size);
    fixup_accum<<<256, 256>>>(train, test, label);
    fixup_write<<<(TEST_P + 255) / 256, 256>>>((float*)d_out, out_size);
}

// round 8
// speedup vs baseline: 14.1264x; 1.4313x over previous
#include <cuda_runtime.h>
#include <cuda_fp16.h>
#include <cstdint>

// ---------------------------------------------------------------------------
// PNN_43095701848191 — int8 IMMA GEMM + tiered (fp16 tensor -> exact fp32)
// fixup for near-tie rows.
//
//  prep:     row L2 norms; per-row symmetric int8 quantization (scale =
//            maxabs/127) AND fp16 copy (for the fixup GEMM); inverse norms.
//  imma:     CTA tile 128x256, K-chunks of 128 s8 (128 B/row, SW128), 4
//            stages as 2 superstages, double-buffered ldmatrix fragments,
//            mma.sync.m16n8k32.s8 (byte-identical fragment layout to f16
//            k16 -> identical addressing). dot = (float)i32 * sa * sb is
//            EXACT given quantized inputs (|i32| < 2^24). Epilogue: Gauss +
//            class sums.
//  finalize: probs + argmax + write; flag |p1-p0| < 4e-4 (~67 sigma of the
//            int8 quantization noise on the gap) -> tier-1 list.
//  fixup16:  gathered fp16 HMMA GEMM over tier-1 rows (full K, 128x64 units).
//  f16write: rewrite tier-1 rows from fp16 sums; flag |gap| < 1e-5 (~52
//            sigma of fp16 noise; proven in round 7) -> tier-2 list.
//  fixup32:  exact fp32 recompute of tier-2 rows; rewrite.
// ---------------------------------------------------------------------------

#define TRAIN_N 8192
#define TEST_P  4096
#define KDIM    1024

#define MT 128
#define NT 256
#define NCHUNK 8              // 8 chunks x 128 s8
#define NSS    (NCHUNK / 2)   // 4 superstages

#define TAU1 4e-4f
#define TAU2 1e-5f
#define NSLICE 32

// quantized planes (s8 packed in uint32) + fp16 planes + scales
__device__ __align__(16) uint32_t g_Aq[TEST_P * KDIM / 4];
__device__ __align__(16) uint32_t g_Bq[TRAIN_N * KDIM / 4];
__device__ __align__(16) __half g_A[TEST_P * KDIM];
__device__ __align__(16) __half g_B[TRAIN_N * KDIM];
__device__ float g_sa[TEST_P];
__device__ float g_sb[TRAIN_N];
__device__ float g_invte[TEST_P];
__device__ float g_invtr[TRAIN_N];
__device__ float g_tot[TEST_P];
__device__ float g_s1[TEST_P];
__device__ int   g_flagged[TEST_P];
__device__ int   g_flaglist[TEST_P];
__device__ int   g_flagcount;
__device__ float g_ftot[TEST_P];
__device__ float g_fs1[TEST_P];
__device__ int   g_flagged2[TEST_P];
__device__ int   g_f2list[TEST_P];
__device__ int   g_f2count;
__device__ float g_f2tot[TEST_P];
__device__ float g_f2s1[TEST_P];

__device__ __forceinline__ uint32_t smem_u32(const void* p) {
    uint32_t a;
    asm("{ .reg .u64 t; cvta.to.shared.u64 t, %1; cvt.u32.u64 %0, t; }"
        : "=r"(a) : "l"(p));
    return a;
}

#define SW128(o) ((o) ^ (((o) >> 3) & 0x70))

#define LDSM4(r0, r1, r2, r3, a) \
    asm volatile("ldmatrix.sync.aligned.m8n8.x4.shared.b16 {%0,%1,%2,%3}, [%4];" \
                 : "=r"(r0), "=r"(r1), "=r"(r2), "=r"(r3) : "r"(a))

#define IMMA16832(d, a, b0, b1) \
    asm volatile("mma.sync.aligned.m16n8k32.row.col.s32.s8.s8.s32 " \
                 "{%0,%1,%2,%3}, {%4,%5,%6,%7}, {%8,%9}, {%0,%1,%2,%3};" \
                 : "+r"((d)[0]), "+r"((d)[1]), "+r"((d)[2]), "+r"((d)[3]) \
                 : "r"((a)[0]), "r"((a)[1]), "r"((a)[2]), "r"((a)[3]), \
                   "r"(b0), "r"(b1))

#define HMMA16816(d, a, b0, b1) \
    asm volatile("mma.sync.aligned.m16n8k16.row.col.f32.f16.f16.f32 " \
                 "{%0,%1,%2,%3}, {%4,%5,%6,%7}, {%8,%9}, {%0,%1,%2,%3};" \
                 : "+f"((d)[0]), "+f"((d)[1]), "+f"((d)[2]), "+f"((d)[3]) \
                 : "r"((a)[0]), "r"((a)[1]), "r"((a)[2]), "r"((a)[3]), \
                   "r"(b0), "r"(b1))

#define EX2(out, in) asm("ex2.approx.f32 %0, %1;" : "=f"(out) : "f"(in))
#define GAUSS_C (-2.885390082f)   /* -2 * log2(e) */

__device__ __forceinline__ float gaussf(float dot) {
    float d2 = fmaxf(2.0f - 2.0f * dot, 0.0f);
    float d;
    asm("sqrt.approx.f32 %0, %1;" : "=f"(d) : "f"(d2));
    float g; EX2(g, GAUSS_C * d);
    return g;
}

// ---------------------------------------------------------------------------
// Kernel 1: norms, int8 quantization + fp16 copy, scales, zero accums.
// ---------------------------------------------------------------------------
__global__ void prep_kernel(const float* __restrict__ train,
                            const float* __restrict__ test) {
    int b = blockIdx.x, t = threadIdx.x;     // 256 threads, 1024 floats/row
    bool isTrain = b < TRAIN_N;
    const float* row = isTrain ? train + (size_t)b * KDIM
                               : test + (size_t)(b - TRAIN_N) * KDIM;
    float4 v = ((const float4*)row)[t];
    float s = v.x * v.x + v.y * v.y + v.z * v.z + v.w * v.w;
    float m = fmaxf(fmaxf(fabsf(v.x), fabsf(v.y)), fmaxf(fabsf(v.z), fabsf(v.w)));
    #pragma unroll
    for (int o = 16; o; o >>= 1) {
        s += __shfl_xor_sync(0xffffffffu, s, o);
        m = fmaxf(m, __shfl_xor_sync(0xffffffffu, m, o));
    }
    __shared__ float ws[8], wm[8];
    __shared__ float s_inv, s_maxn;
    if ((t & 31) == 0) { ws[t >> 5] = s; wm[t >> 5] = m; }
    __syncthreads();
    if (t < 8) {
        float x = ws[t], y = wm[t];
        #pragma unroll
        for (int o = 4; o; o >>= 1) {
            x += __shfl_xor_sync(0xffu, x, o);
            y = fmaxf(y, __shfl_xor_sync(0xffu, y, o));
        }
        if (t == 0) {
            float inv = rsqrtf(x);
            s_inv = inv;
            s_maxn = y * inv;          // max |normalized element|
        }
    }
    __syncthreads();
    float inv = s_inv;
    float qs = 127.0f / s_maxn;        // quantization multiplier

    float x0 = v.x * inv, x1 = v.y * inv, x2 = v.z * inv, x3 = v.w * inv;

    union { __half h[4]; uint2 u; } H;
    H.h[0] = __float2half_rn(x0); H.h[1] = __float2half_rn(x1);
    H.h[2] = __float2half_rn(x2); H.h[3] = __float2half_rn(x3);

    int q0 = __float2int_rn(x0 * qs), q1 = __float2int_rn(x1 * qs);
    int q2 = __float2int_rn(x2 * qs), q3 = __float2int_rn(x3 * qs);
    uint32_t qw = (uint32_t)(q0 & 255) | ((uint32_t)(q1 & 255) << 8) |
                  ((uint32_t)(q2 & 255) << 16) | ((uint32_t)(q3 & 255) << 24);

    if (isTrain) {
        ((uint2*)(g_B + (size_t)b * KDIM))[t] = H.u;
        g_Bq[(size_t)b * 256 + t] = qw;
    } else {
        int bi = b - TRAIN_N;
        ((uint2*)(g_A + (size_t)bi * KDIM))[t] = H.u;
        g_Aq[(size_t)bi * 256 + t] = qw;
    }

    if (t == 0) {
        if (isTrain) {
            g_invtr[b] = inv;
            g_sb[b] = s_maxn * (1.0f / 127.0f);
        } else {
            int bi = b - TRAIN_N;
            g_invte[bi] = inv;
            g_sa[bi] = s_maxn * (1.0f / 127.0f);
            g_tot[bi] = 0.0f;
            g_s1[bi] = 0.0f;
        }
        if (b == 0) { g_flagcount = 0; g_f2count = 0; }
    }
}

// ---------------------------------------------------------------------------
// Kernel 2: int8 IMMA GEMM + PNN epilogue.
// smem: [0,1024) labels f32; [1024,2048) col scales; [2048,2560) row scales;
//       tiles at 3072, 4 x 48 KB.
// ---------------------------------------------------------------------------
#define SLAB_OFF  0
#define SSB_OFF   1024
#define SSA_OFF   2048
#define TILES_OFF 3072
#define STAGE_BYTES (MT * 128 + NT * 128)   // 49152
#define B_OFF       (MT * 128)              // 16384
#define SMEM_TOTAL  (TILES_OFF + 4 * STAGE_BYTES)  // 199680

// load one superstage (2 chunks of 128 B/row) into stages {2*buf, 2*buf+1}
__device__ __forceinline__ void load_ss(int tid, uint32_t sb, int buf,
                                        const char* gA, const char* gB, int ss) {
    #pragma unroll
    for (int h = 0; h < 2; h++) {
        int chunk = 2 * ss + h;
        uint32_t base = sb + TILES_OFF + (uint32_t)(2 * buf + h) * STAGE_BYTES;
        const char* srcA = gA + (size_t)chunk * 128;
        const char* srcB = gB + (size_t)chunk * 128;
        #pragma unroll
        for (int i = 0; i < 12; i++) {
            int u = tid + 256 * i;
            const char* src;
            uint32_t dst;
            if (u < 1024) {                 // A tile: 128 rows x 128 B
                int r = u >> 3, c = u & 7;
                src = srcA + (size_t)r * KDIM + c * 16;   // 1024 B per s8 row
                dst = base + SW128((uint32_t)(r * 128 + c * 16));
            } else {                        // B tile: 256 rows x 128 B
                int vv = u - 1024;
                int r = vv >> 3, c = vv & 7;
                src = srcB + (size_t)r * KDIM + c * 16;
                dst = base + B_OFF + SW128((uint32_t)(r * 128 + c * 16));
            }
            asm volatile("cp.async.cg.shared.global [%0], [%1], 16;"
                         :: "r"(dst), "l"(src));
        }
    }
    asm volatile("cp.async.commit_group;" ::: "memory");
}

// one 32-byte k-step's fragments (layout identical to the f16 path)
__device__ __forceinline__ void ld_frags(uint32_t (&fa)[4][4], uint32_t (&fb)[4][4],
                                         uint32_t stageBase, int ks,
                                         uint32_t aRowOff, uint32_t aHi, uint32_t aXor,
                                         uint32_t bRowOff, uint32_t bHi, uint32_t bXor) {
    uint32_t aoff = ((uint32_t)(ks * 32) + aHi) ^ aXor;
    uint32_t boff = ((uint32_t)(ks * 32) + bHi) ^ bXor;
    uint32_t aBase = stageBase + aRowOff;
    uint32_t bBase = stageBase + B_OFF + bRowOff;
    #pragma unroll
    for (int mi = 0; mi < 4; mi++)
        LDSM4(fa[mi][0], fa[mi][1], fa[mi][2], fa[mi][3], aBase + mi * 2048 + aoff);
    #pragma unroll
    for (int nj = 0; nj < 4; nj++)
        LDSM4(fb[nj][0], fb[nj][1], fb[nj][2], fb[nj][3], bBase + nj * 2048 + boff);
}

__device__ __forceinline__ void imma_step(const uint32_t (&fa)[4][4],
                                          const uint32_t (&fb)[4][4],
                                          int (&acc)[4][8][4]) {
    #pragma unroll
    for (int mi = 0; mi < 4; mi++) {
        #pragma unroll
        for (int nj = 0; nj < 4; nj++) {
            IMMA16832(acc[mi][2 * nj],     fa[mi], fb[nj][0], fb[nj][1]);
            IMMA16832(acc[mi][2 * nj + 1], fa[mi], fb[nj][2], fb[nj][3]);
        }
    }
}

__global__ __launch_bounds__(256)
void pnn_imma(const int* __restrict__ label) {
    extern __shared__ __align__(1024) char smem[];
    uint32_t sb = smem_u32(smem);
    const int tid = threadIdx.x;
    const int wid = tid >> 5, lid = tid & 31;
    const int rowBase = blockIdx.y * MT;      // test rows
    const int colBase = blockIdx.x * NT;      // train rows

    float* slab = (float*)(smem + SLAB_OFF);
    float* ssb  = (float*)(smem + SSB_OFF);
    float* ssa  = (float*)(smem + SSA_OFF);
    slab[tid] = (float)label[colBase + tid];
    ssb[tid]  = g_sb[colBase + tid];
    if (tid < MT) ssa[tid] = g_sa[rowBase + tid];

    const char* gA = (const char*)g_Aq + (size_t)rowBase * KDIM;
    const char* gB = (const char*)g_Bq + (size_t)colBase * KDIM;

    const int wm = (wid >> 2) * 64;
    const int wn = (wid & 3) * 64;

    const int aRow = wm + (lid & 15);
    const uint32_t aXor = (uint32_t)((aRow & 7) << 4);
    const uint32_t aHi  = (uint32_t)(((lid >> 4) & 1) << 4);
    const uint32_t aRowOff = (uint32_t)(aRow * 128);
    const int bRow = wn + (lid & 7) + (((lid >> 4) & 1) << 3);
    const uint32_t bXor = (uint32_t)((bRow & 7) << 4);
    const uint32_t bHi  = (uint32_t)(((lid >> 3) & 1) << 4);
    const uint32_t bRowOff = (uint32_t)(bRow * 128);

    int acc[4][8][4];
    #pragma unroll
    for (int mi = 0; mi < 4; mi++)
        #pragma unroll
        for (int n = 0; n < 8; n++)
            #pragma unroll
            for (int c = 0; c < 4; c++) acc[mi][n][c] = 0;

    load_ss(tid, sb, 0, gA, gB, 0);
    load_ss(tid, sb, 1, gA, gB, 1);
    asm volatile("cp.async.wait_group 1;" ::: "memory");
    __syncthreads();

    uint32_t f0a[4][4], f0b[4][4], f1a[4][4], f1b[4][4];
    ld_frags(f0a, f0b, sb + TILES_OFF, 0, aRowOff, aHi, aXor, bRowOff, bHi, bXor);

    #pragma unroll 1
    for (int c = 0; c < NSS; c++) {
        const int buf = c & 1;
        const uint32_t s0 = sb + TILES_OFF + (uint32_t)(2 * buf) * STAGE_BYTES;
        const uint32_t s1 = s0 + STAGE_BYTES;
        const uint32_t sn = sb + TILES_OFF + (uint32_t)(2 * ((c + 1) & 1)) * STAGE_BYTES;

        ld_frags(f1a, f1b, s0, 1, aRowOff, aHi, aXor, bRowOff, bHi, bXor);
        imma_step(f0a, f0b, acc);
        ld_frags(f0a, f0b, s0, 2, aRowOff, aHi, aXor, bRowOff, bHi, bXor);
        imma_step(f1a, f1b, acc);
        ld_frags(f1a, f1b, s0, 3, aRowOff, aHi, aXor, bRowOff, bHi, bXor);
        imma_step(f0a, f0b, acc);
        ld_frags(f0a, f0b, s1, 0, aRowOff, aHi, aXor, bRowOff, bHi, bXor);
        imma_step(f1a, f1b, acc);
        ld_frags(f1a, f1b, s1, 1, aRowOff, aHi, aXor, bRowOff, bHi, bXor);
        imma_step(f0a, f0b, acc);
        ld_frags(f0a, f0b, s1, 2, aRowOff, aHi, aXor, bRowOff, bHi, bXor);
        imma_step(f1a, f1b, acc);
        ld_frags(f1a, f1b, s1, 3, aRowOff, aHi, aXor, bRowOff, bHi, bXor);
        imma_step(f0a, f0b, acc);

        asm volatile("cp.async.wait_group 0;" ::: "memory");
        __syncthreads();
        if (c + 2 < NSS) load_ss(tid, sb, buf, gA, gB, c + 2);
        if (c + 1 < NSS)
            ld_frags(f0a, f0b, sn, 0, aRowOff, aHi, aXor, bRowOff, bHi, bXor);
        imma_step(f1a, f1b, acc);
    }

    // ---- epilogue: i32 dot -> scaled fp32 (exact: |i32| < 2^24) -> Gauss ----
    #pragma unroll
    for (int mi = 0; mi < 4; mi++) {
        const int r0 = wm + mi * 16 + (lid >> 2);
        const float sa0 = ssa[r0];
        const float sa1 = ssa[r0 + 8];
        float tA = 0.0f, sA = 0.0f, tB = 0.0f, sB = 0.0f;
        #pragma unroll
        for (int n8 = 0; n8 < 8; n8++) {
            #pragma unroll
            for (int j = 0; j < 2; j++) {
                const int col = wn + n8 * 8 + 2 * (lid & 3) + j;
                const float lab = slab[col];
                const float sbv = ssb[col];
                {
                    float g = gaussf((float)acc[mi][n8][j] * (sa0 * sbv));
                    tA += g; sA += g * lab;
                }
                {
                    float g = gaussf((float)acc[mi][n8][2 + j] * (sa1 * sbv));
                    tB += g; sB += g * lab;
                }
            }
        }
        #pragma unroll
        for (int o = 1; o < 4; o <<= 1) {
            tA += __shfl_xor_sync(0xffffffffu, tA, o);
            sA += __shfl_xor_sync(0xffffffffu, sA, o);
            tB += __shfl_xor_sync(0xffffffffu, tB, o);
            sB += __shfl_xor_sync(0xffffffffu, sB, o);
        }
        if ((lid & 3) == 0) {
            int rowA = rowBase + r0;
            atomicAdd(&g_tot[rowA], tA);
            atomicAdd(&g_s1[rowA], sA);
            atomicAdd(&g_tot[rowA + 8], tB);
            atomicAdd(&g_s1[rowA + 8], sB);
        }
    }
}

// ---------------------------------------------------------------------------
// Kernel 3: probs + argmax + write; tier-1 flag.
// ---------------------------------------------------------------------------
__device__ __forceinline__ void write_row(float* out, int out_size, int i,
                                          float p0, float p1) {
    float res = (p1 > p0) ? 1.0f : 0.0f;
    if (out_size >= TEST_P * 3) {
        out[i] = res;
        out[TEST_P + 2 * i]     = p0;
        out[TEST_P + 2 * i + 1] = p1;
    } else if (out_size == TEST_P * 2) {
        out[2 * i] = p0;
        out[2 * i + 1] = p1;
    } else {
        out[i] = res;
    }
}

__global__ void finalize_kernel(float* __restrict__ out, int out_size) {
    int i = blockIdx.x * blockDim.x + threadIdx.x;
    if (i >= TEST_P) return;
    float tot = g_tot[i], s1 = g_s1[i];
    float p0 = (tot - s1) / tot, p1 = s1 / tot;
    write_row(out, out_size, i, p0, p1);
    int fl = (fabsf(p1 - p0) < TAU1) ? 1 : 0;
    g_flagged[i] = fl;
    g_ftot[i] = 0.0f;
    g_fs1[i] = 0.0f;
    if (fl) {
        int idx = atomicAdd(&g_flagcount, 1);
        g_flaglist[idx] = i;
    }
}

// ---------------------------------------------------------------------------
// Kernel 4: gathered fp16 HMMA GEMM over tier-1 rows. Unit = (128-row mtile,
// 64-col ntile), full K. Persistent blocks stride over units.
// ---------------------------------------------------------------------------
__global__ __launch_bounds__(256)
void fixup16_kernel(const int* __restrict__ label) {
    __shared__ int sgrow[128];
    __shared__ float slab2[64];
    __shared__ __align__(1024) char tA[16384];   // 128 rows x 128 B
    __shared__ __align__(1024) char tB[8192];    // 64 rows x 128 B

    const int F = g_flagcount;
    if (F == 0) return;
    const int numM = (F + 127) / 128;
    const int total = numM * 128;                // 128 ntiles of 64 cols
    const int tid = threadIdx.x;
    const int wid = tid >> 5, lid = tid & 31;
    const uint32_t tAb = smem_u32(tA), tBb = smem_u32(tB);

    const int wm = (wid >> 1) * 32;
    const int wn = (wid & 1) * 32;
    const int aRow = wm + (lid & 15);
    const uint32_t aXor = (uint32_t)((aRow & 7) << 4);
    const uint32_t aHi  = (uint32_t)(((lid >> 4) & 1) << 4);
    const uint32_t aRowOff = (uint32_t)(aRow * 128);
    const int bRow = wn + (lid & 7) + (((lid >> 4) & 1) << 3);
    const uint32_t bXor = (uint32_t)((bRow & 7) << 4);
    const uint32_t bHi  = (uint32_t)(((lid >> 3) & 1) << 4);
    const uint32_t bRowOff = (uint32_t)(bRow * 128);

    for (int u = blockIdx.x; u < total; u += gridDim.x) {
        const int mtile = u >> 7;
        const int ntile = u & 127;
        const int colBase = ntile * 64;
        __syncthreads();                         // prior iteration done
        if (tid < 128) {
            int gi = mtile * 128 + tid;
            sgrow[tid] = (gi < F) ? g_flaglist[gi] : 0;
        } else if (tid < 192) {
            slab2[tid - 128] = (float)label[colBase + tid - 128];
        }
        __syncthreads();

        float acc[2][4][4];
        #pragma unroll
        for (int mi = 0; mi < 2; mi++)
            #pragma unroll
            for (int n = 0; n < 4; n++)
                #pragma unroll
                for (int cc = 0; cc < 4; cc++) acc[mi][n][cc] = 0.0f;

        #pragma unroll 1
        for (int chunk = 0; chunk < 16; chunk++) {
            __syncthreads();                     // previous ks reads done
            #pragma unroll
            for (int i = 0; i < 6; i++) {
                int u2 = tid + 256 * i;
                const char* src;
                uint32_t dst;
                if (u2 < 1024) {
                    int r = u2 >> 3, cc = u2 & 7;
                    src = (const char*)g_A + (size_t)sgrow[r] * 2048
                          + chunk * 128 + cc * 16;
                    dst = tAb + SW128((uint32_t)(r * 128 + cc * 16));
                } else {
                    int vv = u2 - 1024;
                    int r = vv >> 3, cc = vv & 7;
                    src = (const char*)g_B + (size_t)(colBase + r) * 2048
                          + chunk * 128 + cc * 16;
                    dst = tBb + SW128((uint32_t)(r * 128 + cc * 16));
                }
                asm volatile("cp.async.cg.shared.global [%0], [%1], 16;"
                             :: "r"(dst), "l"(src));
            }
            asm volatile("cp.async.commit_group;" ::: "memory");
            asm volatile("cp.async.wait_group 0;" ::: "memory");
            __syncthreads();
            #pragma unroll
            for (int ks = 0; ks < 4; ks++) {
                uint32_t aoff = ((uint32_t)(ks * 32) + aHi) ^ aXor;
                uint32_t boff = ((uint32_t)(ks * 32) + bHi) ^ bXor;
                uint32_t fa[2][4], fb[2][4];
                #pragma unroll
                for (int mi = 0; mi < 2; mi++)
                    LDSM4(fa[mi][0], fa[mi][1], fa[mi][2], fa[mi][3],
                          tAb + aRowOff + mi * 2048 + aoff);
                #pragma unroll
                for (int nj = 0; nj < 2; nj++)
                    LDSM4(fb[nj][0], fb[nj][1], fb[nj][2], fb[nj][3],
                          tBb + bRowOff + nj * 2048 + boff);
                #pragma unroll
                for (int mi = 0; mi < 2; mi++)
                    #pragma unroll
                    for (int nj = 0; nj < 2; nj++) {
                        HMMA16816(acc[mi][2 * nj],     fa[mi], fb[nj][0], fb[nj][1]);
                        HMMA16816(acc[mi][2 * nj + 1], fa[mi], fb[nj][2], fb[nj][3]);
                    }
            }
        }

        // epilogue
        #pragma unroll
        for (int mi = 0; mi < 2; mi++) {
            const int r0 = wm + mi * 16 + (lid >> 2);
            float tAcc = 0.0f, sAcc = 0.0f, tBcc = 0.0f, sBcc = 0.0f;
            #pragma unroll
            for (int n8 = 0; n8 < 4; n8++) {
                #pragma unroll
                for (int j = 0; j < 2; j++) {
                    float lab = slab2[wn + n8 * 8 + 2 * (lid & 3) + j];
                    float g0 = gaussf(acc[mi][n8][j]);
                    tAcc += g0; sAcc += g0 * lab;
                    float g1 = gaussf(acc[mi][n8][2 + j]);
                    tBcc += g1; sBcc += g1 * lab;
                }
            }
            #pragma unroll
            for (int o = 1; o < 4; o <<= 1) {
                tAcc += __shfl_xor_sync(0xffffffffu, tAcc, o);
                sAcc += __shfl_xor_sync(0xffffffffu, sAcc, o);
                tBcc += __shfl_xor_sync(0xffffffffu, tBcc, o);
                sBcc += __shfl_xor_sync(0xffffffffu, sBcc, o);
            }
            if ((lid & 3) == 0) {
                if (mtile * 128 + r0 < F) {
                    int row = sgrow[r0];
                    atomicAdd(&g_ftot[row], tAcc);
                    atomicAdd(&g_fs1[row], sAcc);
                }
                if (mtile * 128 + r0 + 8 < F) {
                    int row = sgrow[r0 + 8];
                    atomicAdd(&g_ftot[row], tBcc);
                    atomicAdd(&g_fs1[row], sBcc);
                }
            }
        }
    }
}

// ---------------------------------------------------------------------------
// Kernel 5: rewrite tier-1 rows from fp16 sums; tier-2 flag.
// ---------------------------------------------------------------------------
__global__ void fixup16_write(float* __restrict__ out, int out_size) {
    int i = blockIdx.x * blockDim.x + threadIdx.x;
    if (i >= TEST_P) return;
    if (!g_flagged[i]) { g_flagged2[i] = 0; return; }
    float tot = g_ftot[i], s1 = g_fs1[i];
    float p0 = (tot - s1) / tot, p1 = s1 / tot;
    write_row(out, out_size, i, p0, p1);
    int fl2 = (fabsf(p1 - p0) < TAU2) ? 1 : 0;
    g_flagged2[i] = fl2;
    if (fl2) {
        int idx = atomicAdd(&g_f2count, 1);
        g_f2list[idx] = i;
        g_f2tot[i] = 0.0f;
        g_f2s1[i] = 0.0f;
    }
}

// ---------------------------------------------------------------------------
// Kernel 6: exact fp32 recompute for tier-2 rows.
// ---------------------------------------------------------------------------
__global__ void fixup32_accum(const float* __restrict__ train,
                              const float* __restrict__ test,
                              const int* __restrict__ label) {
    __shared__ float sa[KDIM];
    int total = g_f2count * NSLICE;
    for (int w = blockIdx.x; w < total; w += gridDim.x) {
        int row   = g_f2list[w / NSLICE];
        int slice = w % NSLICE;
        float ivte = g_invte[row];
        __syncthreads();
        for (int i = threadIdx.x; i < KDIM; i += 256)
            sa[i] = test[(size_t)row * KDIM + i] * ivte;
        __syncthreads();
        int wid = threadIdx.x >> 5, lid = threadIdx.x & 31;
        float tot = 0.0f, s1 = 0.0f;
        for (int r = 0; r < 32; r++) {
            int trow = slice * 256 + wid * 32 + r;
            const float* brow = train + (size_t)trow * KDIM;
            float d = 0.0f;
            #pragma unroll 8
            for (int i = lid; i < KDIM; i += 32) d += sa[i] * brow[i];
            #pragma unroll
            for (int o = 16; o; o >>= 1) d += __shfl_xor_sync(0xffffffffu, d, o);
            if (lid == 0) {
                float dot = d * g_invtr[trow];
                float d2 = fmaxf(2.0f - 2.0f * dot, 0.0f);
                float g = __expf(-2.0f * sqrtf(d2));
                tot += g;
                s1  += g * (float)label[trow];
            }
        }
        if (lid == 0) {
            atomicAdd(&g_f2tot[row], tot);
            atomicAdd(&g_f2s1[row], s1);
        }
    }
}

__global__ void fixup32_write(float* __restrict__ out, int out_size) {
    int i = blockIdx.x * blockDim.x + threadIdx.x;
    if (i >= TEST_P || !g_flagged2[i]) return;
    float tot = g_f2tot[i], s1 = g_f2s1[i];
    write_row(out, out_size, i, (tot - s1) / tot, s1 / tot);
}

extern "C" void kernel_launch(void* const* d_in, const int* in_sizes, int n_in,
                              void* d_out, int out_size) {
    const float* train = (const float*)d_in[0];
    const int*   label = (const int*)d_in[1];
    const float* test  = (const float*)d_in[2];

    cudaFuncSetAttribute(pnn_imma, cudaFuncAttributeMaxDynamicSharedMemorySize,
                         SMEM_TOTAL);

    prep_kernel<<<TRAIN_N + TEST_P, 256>>>(train, test);

    dim3 grid(TRAIN_N / NT, TEST_P / MT);   // (32, 32)
    pnn_imma<<<grid, 256, SMEM_TOTAL>>>(label);

    finalize_kernel<<<(TEST_P + 255) / 256, 256>>>((float*)d_out, out_size);
    fixup16_kernel<<<256, 256>>>(label);
    fixup16_write<<<(TEST_P + 255) / 256, 256>>>((float*)d_out, out_size);
    fixup32_accum<<<256, 256>>>(train, test, label);
    fixup32_write<<<(TEST_P + 255) / 256, 256>>>((float*)d_out, out_size);
}

// round 9
// speedup vs baseline: 15.0682x; 1.0667x over previous
#include <cuda_runtime.h>
#include <cuda_fp16.h>
#include <cstdint>

// ---------------------------------------------------------------------------
// PNN_43095701848191 — int8 IMMA GEMM (128x128 tiles, 2 CTAs/SM so epilogue
// overlaps the co-resident CTA's mainloop) + tiered (fp16 -> exact fp32)
// fixup for near-tie rows.
//
//  prep:     row L2 norms; per-row symmetric int8 quantization only
//            (scale = maxabs/127); inverse norms.
//  imma:     CTA tile 128x128, K-chunks of 128 s8 (128 B/row, SW128),
//            3-stage cp.async pipeline, mma.sync.m16n8k32.s8. dot =
//            (float)i32 * sa * sb is EXACT (|i32| < 2^24). Epilogue:
//            Gauss + per-class sums (atomics).
//  finalize: probs + argmax + write; flag |p1-p0| < 4e-4 (~67 sigma of
//            int8 gap noise) -> tier-1 list.
//  fixup16:  gathered fp16 HMMA GEMM over tier-1 rows, converting f32->f16
//            on the fly (LDG + cvt + STS).
//  f16write: rewrite tier-1 rows; flag |gap| < 1e-5 (52 sigma fp16 noise,
//            proven in round 7) -> tier-2.
//  fixup32:  exact fp32 recompute of tier-2 rows; rewrite.
// ---------------------------------------------------------------------------

#define TRAIN_N 8192
#define TEST_P  4096
#define KDIM    1024

#define MT 128
#define NT 128
#define NCHUNK 8              // 8 chunks x 128 s8
#define STAGES 3

#define TAU1 4e-4f
#define TAU2 1e-5f
#define NSLICE 32

__device__ __align__(16) uint32_t g_Aq[TEST_P * KDIM / 4];
__device__ __align__(16) uint32_t g_Bq[TRAIN_N * KDIM / 4];
__device__ float g_sa[TEST_P];
__device__ float g_sb[TRAIN_N];
__device__ float g_invte[TEST_P];
__device__ float g_invtr[TRAIN_N];
__device__ float g_tot[TEST_P];
__device__ float g_s1[TEST_P];
__device__ int   g_flagged[TEST_P];
__device__ int   g_flaglist[TEST_P];
__device__ int   g_flagcount;
__device__ float g_ftot[TEST_P];
__device__ float g_fs1[TEST_P];
__device__ int   g_flagged2[TEST_P];
__device__ int   g_f2list[TEST_P];
__device__ int   g_f2count;
__device__ float g_f2tot[TEST_P];
__device__ float g_f2s1[TEST_P];

__device__ __forceinline__ uint32_t smem_u32(const void* p) {
    uint32_t a;
    asm("{ .reg .u64 t; cvta.to.shared.u64 t, %1; cvt.u32.u64 %0, t; }"
        : "=r"(a) : "l"(p));
    return a;
}

#define SW128(o) ((o) ^ (((o) >> 3) & 0x70))

#define LDSM4(r0, r1, r2, r3, a) \
    asm volatile("ldmatrix.sync.aligned.m8n8.x4.shared.b16 {%0,%1,%2,%3}, [%4];" \
                 : "=r"(r0), "=r"(r1), "=r"(r2), "=r"(r3) : "r"(a))

#define IMMA16832(d, a, b0, b1) \
    asm volatile("mma.sync.aligned.m16n8k32.row.col.s32.s8.s8.s32 " \
                 "{%0,%1,%2,%3}, {%4,%5,%6,%7}, {%8,%9}, {%0,%1,%2,%3};" \
                 : "+r"((d)[0]), "+r"((d)[1]), "+r"((d)[2]), "+r"((d)[3]) \
                 : "r"((a)[0]), "r"((a)[1]), "r"((a)[2]), "r"((a)[3]), \
                   "r"(b0), "r"(b1))

#define HMMA16816(d, a, b0, b1) \
    asm volatile("mma.sync.aligned.m16n8k16.row.col.f32.f16.f16.f32 " \
                 "{%0,%1,%2,%3}, {%4,%5,%6,%7}, {%8,%9}, {%0,%1,%2,%3};" \
                 : "+f"((d)[0]), "+f"((d)[1]), "+f"((d)[2]), "+f"((d)[3]) \
                 : "r"((a)[0]), "r"((a)[1]), "r"((a)[2]), "r"((a)[3]), \
                   "r"(b0), "r"(b1))

#define EX2(out, in) asm("ex2.approx.f32 %0, %1;" : "=f"(out) : "f"(in))
#define GAUSS_C (-2.885390082f)   /* -2 * log2(e) */

__device__ __forceinline__ float gaussf(float dot) {
    float d2 = fmaxf(2.0f - 2.0f * dot, 0.0f);
    float d;
    asm("sqrt.approx.f32 %0, %1;" : "=f"(d) : "f"(d2));
    float g; EX2(g, GAUSS_C * d);
    return g;
}

// ---------------------------------------------------------------------------
// Kernel 1: norms, int8 quantization, scales, zero accumulators.
// ---------------------------------------------------------------------------
__global__ void prep_kernel(const float* __restrict__ train,
                            const float* __restrict__ test) {
    int b = blockIdx.x, t = threadIdx.x;     // 256 threads, 1024 floats/row
    bool isTrain = b < TRAIN_N;
    const float* row = isTrain ? train + (size_t)b * KDIM
                               : test + (size_t)(b - TRAIN_N) * KDIM;
    float4 v = ((const float4*)row)[t];
    float s = v.x * v.x + v.y * v.y + v.z * v.z + v.w * v.w;
    float m = fmaxf(fmaxf(fabsf(v.x), fabsf(v.y)), fmaxf(fabsf(v.z), fabsf(v.w)));
    #pragma unroll
    for (int o = 16; o; o >>= 1) {
        s += __shfl_xor_sync(0xffffffffu, s, o);
        m = fmaxf(m, __shfl_xor_sync(0xffffffffu, m, o));
    }
    __shared__ float ws[8], wm[8];
    __shared__ float s_inv, s_maxn;
    if ((t & 31) == 0) { ws[t >> 5] = s; wm[t >> 5] = m; }
    __syncthreads();
    if (t < 8) {
        float x = ws[t], y = wm[t];
        #pragma unroll
        for (int o = 4; o; o >>= 1) {
            x += __shfl_xor_sync(0xffu, x, o);
            y = fmaxf(y, __shfl_xor_sync(0xffu, y, o));
        }
        if (t == 0) {
            float inv = rsqrtf(x);
            s_inv = inv;
            s_maxn = y * inv;
        }
    }
    __syncthreads();
    float inv = s_inv;
    float qs = 127.0f / s_maxn;

    int q0 = __float2int_rn(v.x * inv * qs), q1 = __float2int_rn(v.y * inv * qs);
    int q2 = __float2int_rn(v.z * inv * qs), q3 = __float2int_rn(v.w * inv * qs);
    uint32_t qw = (uint32_t)(q0 & 255) | ((uint32_t)(q1 & 255) << 8) |
                  ((uint32_t)(q2 & 255) << 16) | ((uint32_t)(q3 & 255) << 24);

    if (isTrain) g_Bq[(size_t)b * 256 + t] = qw;
    else         g_Aq[(size_t)(b - TRAIN_N) * 256 + t] = qw;

    if (t == 0) {
        if (isTrain) {
            g_invtr[b] = inv;
            g_sb[b] = s_maxn * (1.0f / 127.0f);
        } else {
            int bi = b - TRAIN_N;
            g_invte[bi] = inv;
            g_sa[bi] = s_maxn * (1.0f / 127.0f);
            g_tot[bi] = 0.0f;
            g_s1[bi] = 0.0f;
        }
        if (b == 0) { g_flagcount = 0; g_f2count = 0; }
    }
}

// ---------------------------------------------------------------------------
// Kernel 2: int8 IMMA GEMM, 128x128 tile, 2 CTAs/SM.
// smem: [0,512) labels; [512,1024) col scales; [1024,1536) row scales;
//       tiles at 2048, 3 x 32 KB.
// ---------------------------------------------------------------------------
#define SLAB_OFF  0
#define SSB_OFF   512
#define SSA_OFF   1024
#define TILES_OFF 2048
#define STAGE_BYTES (MT * 128 + NT * 128)   // 32768
#define B_OFF       (MT * 128)              // 16384
#define SMEM_TOTAL  (TILES_OFF + STAGES * STAGE_BYTES)  // 100352

__device__ __forceinline__ void load_chunk(int tid, uint32_t sb, int stage,
                                           const char* gA, const char* gB,
                                           int chunk) {
    uint32_t base = sb + TILES_OFF + (uint32_t)stage * STAGE_BYTES;
    const char* srcA = gA + (size_t)chunk * 128;
    const char* srcB = gB + (size_t)chunk * 128;
    #pragma unroll
    for (int i = 0; i < 8; i++) {
        int u = tid + 256 * i;
        const char* src;
        uint32_t dst;
        if (u < 1024) {                 // A tile: 128 rows x 128 B
            int r = u >> 3, c = u & 7;
            src = srcA + (size_t)r * KDIM + c * 16;
            dst = base + SW128((uint32_t)(r * 128 + c * 16));
        } else {                        // B tile: 128 rows x 128 B
            int vv = u - 1024;
            int r = vv >> 3, c = vv & 7;
            src = srcB + (size_t)r * KDIM + c * 16;
            dst = base + B_OFF + SW128((uint32_t)(r * 128 + c * 16));
        }
        asm volatile("cp.async.cg.shared.global [%0], [%1], 16;"
                     :: "r"(dst), "l"(src));
    }
    asm volatile("cp.async.commit_group;" ::: "memory");
}

__global__ __launch_bounds__(256, 2)
void pnn_imma(const int* __restrict__ label) {
    extern __shared__ __align__(1024) char smem[];
    uint32_t sb = smem_u32(smem);
    const int tid = threadIdx.x;
    const int wid = tid >> 5, lid = tid & 31;
    const int rowBase = blockIdx.y * MT;      // test rows
    const int colBase = blockIdx.x * NT;      // train rows

    float* slab = (float*)(smem + SLAB_OFF);
    float* ssb  = (float*)(smem + SSB_OFF);
    float* ssa  = (float*)(smem + SSA_OFF);
    if (tid < NT)            slab[tid] = (float)label[colBase + tid];
    else if (tid < 2 * NT)   ssb[tid - NT] = g_sb[colBase + tid - NT];
    // row scales (128) loaded by the same 256 threads, second pass:
    if (tid < MT)            ssa[tid] = g_sa[rowBase + tid];

    const char* gA = (const char*)g_Aq + (size_t)rowBase * KDIM;
    const char* gB = (const char*)g_Bq + (size_t)colBase * KDIM;

    // warp layout: 4 (m) x 2 (n); warp tile 32 x 64
    const int wm = (wid >> 1) * 32;
    const int wn = (wid & 1) * 64;

    const int aRow = wm + (lid & 15);
    const uint32_t aXor = (uint32_t)((aRow & 7) << 4);
    const uint32_t aHi  = (uint32_t)(((lid >> 4) & 1) << 4);
    const uint32_t aRowOff = (uint32_t)(aRow * 128);
    const int bRow = wn + (lid & 7) + (((lid >> 4) & 1) << 3);
    const uint32_t bXor = (uint32_t)((bRow & 7) << 4);
    const uint32_t bHi  = (uint32_t)(((lid >> 3) & 1) << 4);
    const uint32_t bRowOff = (uint32_t)(bRow * 128);

    int acc[2][8][4];
    #pragma unroll
    for (int mi = 0; mi < 2; mi++)
        #pragma unroll
        for (int n = 0; n < 8; n++)
            #pragma unroll
            for (int c = 0; c < 4; c++) acc[mi][n][c] = 0;

    load_chunk(tid, sb, 0, gA, gB, 0);
    load_chunk(tid, sb, 1, gA, gB, 1);

    #pragma unroll 1
    for (int t = 0; t < NCHUNK; t++) {
        if (t + 1 < NCHUNK) {
            asm volatile("cp.async.wait_group 1;" ::: "memory");
        } else {
            asm volatile("cp.async.wait_group 0;" ::: "memory");
        }
        __syncthreads();
        if (t + 2 < NCHUNK)
            load_chunk(tid, sb, (t + 2) % STAGES, gA, gB, t + 2);

        const uint32_t base = sb + TILES_OFF + (uint32_t)(t % STAGES) * STAGE_BYTES;
        #pragma unroll
        for (int ks = 0; ks < 4; ks++) {
            uint32_t aoff = ((uint32_t)(ks * 32) + aHi) ^ aXor;
            uint32_t boff = ((uint32_t)(ks * 32) + bHi) ^ bXor;
            uint32_t fa[2][4], fb[4][4];
            #pragma unroll
            for (int mi = 0; mi < 2; mi++)
                LDSM4(fa[mi][0], fa[mi][1], fa[mi][2], fa[mi][3],
                      base + aRowOff + mi * 2048 + aoff);
            #pragma unroll
            for (int nj = 0; nj < 4; nj++)
                LDSM4(fb[nj][0], fb[nj][1], fb[nj][2], fb[nj][3],
                      base + B_OFF + bRowOff + nj * 2048 + boff);
            #pragma unroll
            for (int mi = 0; mi < 2; mi++)
                #pragma unroll
                for (int nj = 0; nj < 4; nj++) {
                    IMMA16832(acc[mi][2 * nj],     fa[mi], fb[nj][0], fb[nj][1]);
                    IMMA16832(acc[mi][2 * nj + 1], fa[mi], fb[nj][2], fb[nj][3]);
                }
        }
    }

    // ---- epilogue: i32 -> scaled fp32 dot (exact) -> Gauss -> class sums ----
    #pragma unroll
    for (int mi = 0; mi < 2; mi++) {
        const int r0 = wm + mi * 16 + (lid >> 2);
        const float sa0 = ssa[r0];
        const float sa1 = ssa[r0 + 8];
        float tA = 0.0f, sA = 0.0f, tB = 0.0f, sB = 0.0f;
        #pragma unroll
        for (int n8 = 0; n8 < 8; n8++) {
            #pragma unroll
            for (int j = 0; j < 2; j++) {
                const int col = wn + n8 * 8 + 2 * (lid & 3) + j;
                const float lab = slab[col];
                const float sbv = ssb[col];
                {
                    float g = gaussf((float)acc[mi][n8][j] * (sa0 * sbv));
                    tA += g; sA += g * lab;
                }
                {
                    float g = gaussf((float)acc[mi][n8][2 + j] * (sa1 * sbv));
                    tB += g; sB += g * lab;
                }
            }
        }
        #pragma unroll
        for (int o = 1; o < 4; o <<= 1) {
            tA += __shfl_xor_sync(0xffffffffu, tA, o);
            sA += __shfl_xor_sync(0xffffffffu, sA, o);
            tB += __shfl_xor_sync(0xffffffffu, tB, o);
            sB += __shfl_xor_sync(0xffffffffu, sB, o);
        }
        if ((lid & 3) == 0) {
            int rowA = rowBase + r0;
            atomicAdd(&g_tot[rowA], tA);
            atomicAdd(&g_s1[rowA], sA);
            atomicAdd(&g_tot[rowA + 8], tB);
            atomicAdd(&g_s1[rowA + 8], sB);
        }
    }
}

// ---------------------------------------------------------------------------
// Kernel 3: probs + argmax + write; tier-1 flag.
// ---------------------------------------------------------------------------
__device__ __forceinline__ void write_row(float* out, int out_size, int i,
                                          float p0, float p1) {
    float res = (p1 > p0) ? 1.0f : 0.0f;
    if (out_size >= TEST_P * 3) {
        out[i] = res;
        out[TEST_P + 2 * i]     = p0;
        out[TEST_P + 2 * i + 1] = p1;
    } else if (out_size == TEST_P * 2) {
        out[2 * i] = p0;
        out[2 * i + 1] = p1;
    } else {
        out[i] = res;
    }
}

__global__ void finalize_kernel(float* __restrict__ out, int out_size) {
    int i = blockIdx.x * blockDim.x + threadIdx.x;
    if (i >= TEST_P) return;
    float tot = g_tot[i], s1 = g_s1[i];
    float p0 = (tot - s1) / tot, p1 = s1 / tot;
    write_row(out, out_size, i, p0, p1);
    int fl = (fabsf(p1 - p0) < TAU1) ? 1 : 0;
    g_flagged[i] = fl;
    g_ftot[i] = 0.0f;
    g_fs1[i] = 0.0f;
    if (fl) {
        int idx = atomicAdd(&g_flagcount, 1);
        g_flaglist[idx] = i;
    }
}

// ---------------------------------------------------------------------------
// Kernel 4: gathered fp16 HMMA GEMM over tier-1 rows; f32 -> f16 on the fly.
// Unit = (128-row mtile, 64-col ntile), full K.
// ---------------------------------------------------------------------------
__global__ __launch_bounds__(256)
void fixup16_kernel(const float* __restrict__ train,
                    const float* __restrict__ test,
                    const int* __restrict__ label) {
    __shared__ int sgrow[128];
    __shared__ float sinvA[128];
    __shared__ float sinvB[64];
    __shared__ float slab2[64];
    __shared__ __align__(1024) char tA[16384];   // 128 rows x 128 B (f16)
    __shared__ __align__(1024) char tB[8192];    // 64 rows x 128 B (f16)

    const int F = g_flagcount;
    if (F == 0) return;
    const int numM = (F + 127) / 128;
    const int total = numM * 128;                // 128 ntiles of 64 cols
    const int tid = threadIdx.x;
    const int wid = tid >> 5, lid = tid & 31;
    const uint32_t tAb = smem_u32(tA), tBb = smem_u32(tB);

    const int wm = (wid >> 1) * 32;
    const int wn = (wid & 1) * 32;
    const int aRow = wm + (lid & 15);
    const uint32_t aXor = (uint32_t)((aRow & 7) << 4);
    const uint32_t aHi  = (uint32_t)(((lid >> 4) & 1) << 4);
    const uint32_t aRowOff = (uint32_t)(aRow * 128);
    const int bRow = wn + (lid & 7) + (((lid >> 4) & 1) << 3);
    const uint32_t bXor = (uint32_t)((bRow & 7) << 4);
    const uint32_t bHi  = (uint32_t)(((lid >> 3) & 1) << 4);
    const uint32_t bRowOff = (uint32_t)(bRow * 128);

    for (int u = blockIdx.x; u < total; u += gridDim.x) {
        const int mtile = u >> 7;
        const int ntile = u & 127;
        const int colBase = ntile * 64;
        __syncthreads();
        if (tid < 128) {
            int gi = mtile * 128 + tid;
            int row = (gi < F) ? g_flaglist[gi] : 0;
            sgrow[tid] = row;
            sinvA[tid] = g_invte[row];
        } else if (tid < 192) {
            slab2[tid - 128] = (float)label[colBase + tid - 128];
            sinvB[tid - 128] = g_invtr[colBase + tid - 128];
        }
        __syncthreads();

        float acc[2][4][4];
        #pragma unroll
        for (int mi = 0; mi < 2; mi++)
            #pragma unroll
            for (int n = 0; n < 4; n++)
                #pragma unroll
                for (int cc = 0; cc < 4; cc++) acc[mi][n][cc] = 0.0f;

        #pragma unroll 1
        for (int chunk = 0; chunk < 16; chunk++) {
            __syncthreads();                     // previous ks reads done
            // 1536 16-B units: A 128x8, B 64x8; LDG f32 -> cvt -> STS f16
            #pragma unroll
            for (int i = 0; i < 6; i++) {
                int u2 = tid + 256 * i;
                int r, cc;
                const float* src;
                float inv;
                uint32_t dst;
                if (u2 < 1024) {
                    r = u2 >> 3; cc = u2 & 7;
                    src = test + (size_t)sgrow[r] * KDIM + chunk * 64 + cc * 8;
                    inv = sinvA[r];
                    dst = tAb + SW128((uint32_t)(r * 128 + cc * 16));
                } else {
                    int vv = u2 - 1024;
                    r = vv >> 3; cc = vv & 7;
                    src = train + (size_t)(colBase + r) * KDIM + chunk * 64 + cc * 8;
                    inv = sinvB[r];
                    dst = tBb + SW128((uint32_t)(r * 128 + cc * 16));
                }
                float4 v0 = ((const float4*)src)[0];
                float4 v1 = ((const float4*)src)[1];
                union { __half h[8]; uint4 q; } H;
                H.h[0] = __float2half_rn(v0.x * inv);
                H.h[1] = __float2half_rn(v0.y * inv);
                H.h[2] = __float2half_rn(v0.z * inv);
                H.h[3] = __float2half_rn(v0.w * inv);
                H.h[4] = __float2half_rn(v1.x * inv);
                H.h[5] = __float2half_rn(v1.y * inv);
                H.h[6] = __float2half_rn(v1.z * inv);
                H.h[7] = __float2half_rn(v1.w * inv);
                asm volatile("st.shared.v4.b32 [%0], {%1,%2,%3,%4};"
                             :: "r"(dst), "r"(H.q.x), "r"(H.q.y),
                                "r"(H.q.z), "r"(H.q.w) : "memory");
            }
            __syncthreads();
            #pragma unroll
            for (int ks = 0; ks < 4; ks++) {
                uint32_t aoff = ((uint32_t)(ks * 32) + aHi) ^ aXor;
                uint32_t boff = ((uint32_t)(ks * 32) + bHi) ^ bXor;
                uint32_t fa[2][4], fb[2][4];
                #pragma unroll
                for (int mi = 0; mi < 2; mi++)
                    LDSM4(fa[mi][0], fa[mi][1], fa[mi][2], fa[mi][3],
                          tAb + aRowOff + mi * 2048 + aoff);
                #pragma unroll
                for (int nj = 0; nj < 2; nj++)
                    LDSM4(fb[nj][0], fb[nj][1], fb[nj][2], fb[nj][3],
                          tBb + bRowOff + nj * 2048 + boff);
                #pragma unroll
                for (int mi = 0; mi < 2; mi++)
                    #pragma unroll
                    for (int nj = 0; nj < 2; nj++) {
                        HMMA16816(acc[mi][2 * nj],     fa[mi], fb[nj][0], fb[nj][1]);
                        HMMA16816(acc[mi][2 * nj + 1], fa[mi], fb[nj][2], fb[nj][3]);
                    }
            }
        }

        #pragma unroll
        for (int mi = 0; mi < 2; mi++) {
            const int r0 = wm + mi * 16 + (lid >> 2);
            float tAcc = 0.0f, sAcc = 0.0f, tBcc = 0.0f, sBcc = 0.0f;
            #pragma unroll
            for (int n8 = 0; n8 < 4; n8++) {
                #pragma unroll
                for (int j = 0; j < 2; j++) {
                    float lab = slab2[wn + n8 * 8 + 2 * (lid & 3) + j];
                    float g0 = gaussf(acc[mi][n8][j]);
                    tAcc += g0; sAcc += g0 * lab;
                    float g1 = gaussf(acc[mi][n8][2 + j]);
                    tBcc += g1; sBcc += g1 * lab;
                }
            }
            #pragma unroll
            for (int o = 1; o < 4; o <<= 1) {
                tAcc += __shfl_xor_sync(0xffffffffu, tAcc, o);
                sAcc += __shfl_xor_sync(0xffffffffu, sAcc, o);
                tBcc += __shfl_xor_sync(0xffffffffu, tBcc, o);
                sBcc += __shfl_xor_sync(0xffffffffu, sBcc, o);
            }
            if ((lid & 3) == 0) {
                if (mtile * 128 + r0 < F) {
                    int row = sgrow[r0];
                    atomicAdd(&g_ftot[row], tAcc);
                    atomicAdd(&g_fs1[row], sAcc);
                }
                if (mtile * 128 + r0 + 8 < F) {
                    int row = sgrow[r0 + 8];
                    atomicAdd(&g_ftot[row], tBcc);
                    atomicAdd(&g_fs1[row], sBcc);
                }
            }
        }
    }
}

// ---------------------------------------------------------------------------
// Kernel 5: rewrite tier-1 rows from fp16 sums; tier-2 flag.
// ---------------------------------------------------------------------------
__global__ void fixup16_write(float* __restrict__ out, int out_size) {
    int i = blockIdx.x * blockDim.x + threadIdx.x;
    if (i >= TEST_P) return;
    if (!g_flagged[i]) { g_flagged2[i] = 0; return; }
    float tot = g_ftot[i], s1 = g_fs1[i];
    float p0 = (tot - s1) / tot, p1 = s1 / tot;
    write_row(out, out_size, i, p0, p1);
    int fl2 = (fabsf(p1 - p0) < TAU2) ? 1 : 0;
    g_flagged2[i] = fl2;
    if (fl2) {
        int idx = atomicAdd(&g_f2count, 1);
        g_f2list[idx] = i;
        g_f2tot[i] = 0.0f;
        g_f2s1[i] = 0.0f;
    }
}

// ---------------------------------------------------------------------------
// Kernel 6: exact fp32 recompute for tier-2 rows.
// ---------------------------------------------------------------------------
__global__ void fixup32_accum(const float* __restrict__ train,
                              const float* __restrict__ test,
                              const int* __restrict__ label) {
    __shared__ float sa[KDIM];
    int total = g_f2count * NSLICE;
    for (int w = blockIdx.x; w < total; w += gridDim.x) {
        int row   = g_f2list[w / NSLICE];
        int slice = w % NSLICE;
        float ivte = g_invte[row];
        __syncthreads();
        for (int i = threadIdx.x; i < KDIM; i += 256)
            sa[i] = test[(size_t)row * KDIM + i] * ivte;
        __syncthreads();
        int wid = threadIdx.x >> 5, lid = threadIdx.x & 31;
        float tot = 0.0f, s1 = 0.0f;
        for (int r = 0; r < 32; r++) {
            int trow = slice * 256 + wid * 32 + r;
            const float* brow = train + (size_t)trow * KDIM;
            float d = 0.0f;
            #pragma unroll 8
            for (int i = lid; i < KDIM; i += 32) d += sa[i] * brow[i];
            #pragma unroll
            for (int o = 16; o; o >>= 1) d += __shfl_xor_sync(0xffffffffu, d, o);
            if (lid == 0) {
                float dot = d * g_invtr[trow];
                float d2 = fmaxf(2.0f - 2.0f * dot, 0.0f);
                float g = __expf(-2.0f * sqrtf(d2));
                tot += g;
                s1  += g * (float)label[trow];
            }
        }
        if (lid == 0) {
            atomicAdd(&g_f2tot[row], tot);
            atomicAdd(&g_f2s1[row], s1);
        }
    }
}

__global__ void fixup32_write(float* __restrict__ out, int out_size) {
    int i = blockIdx.x * blockDim.x + threadIdx.x;
    if (i >= TEST_P || !g_flagged2[i]) return;
    float tot = g_f2tot[i], s1 = g_f2s1[i];
    write_row(out, out_size, i, (tot - s1) / tot, s1 / tot);
}

extern "C" void kernel_launch(void* const* d_in, const int* in_sizes, int n_in,
                              void* d_out, int out_size) {
    const float* train = (const float*)d_in[0];
    const int*   label = (const int*)d_in[1];
    const float* test  = (const float*)d_in[2];

    cudaFuncSetAttribute(pnn_imma, cudaFuncAttributeMaxDynamicSharedMemorySize,
                         SMEM_TOTAL);

    prep_kernel<<<TRAIN_N + TEST_P, 256>>>(train, test);

    dim3 grid(TRAIN_N / NT, TEST_P / MT);   // (64, 32)
    pnn_imma<<<grid, 256, SMEM_TOTAL>>>(label);

    finalize_kernel<<<(TEST_P + 255) / 256, 256>>>((float*)d_out, out_size);
    fixup16_kernel<<<256, 256>>>(train, test, label);
    fixup16_write<<<(TEST_P + 255) / 256, 256>>>((float*)d_out, out_size);
    fixup32_accum<<<256, 256>>>(train, test, label);
    fixup32_write<<<(TEST_P + 255) / 256, 256>>>((float*)d_out, out_size);
}